// round 1
// baseline (speedup 1.0000x reference)
#include <cuda_runtime.h>
#include <math.h>

#define BB   2
#define NN   2048
#define HID  896
#define HQ   14
#define HKV  2
#define DD   64
#define MTOT (BB*NN)          // 4096 tokens

// ---- scratch (device globals: no allocations allowed) ----
__device__ float g_q[MTOT*HQ*DD];    // [B,N,HQ,D]  14 MB
__device__ float g_k[MTOT*HKV*DD];   // [B,N,HKV,D]  2 MB
__device__ float g_v[MTOT*HKV*DD];   //              2 MB
__device__ float g_o[MTOT*HQ*DD];    // attention out, [B,N,HQ,D] 14 MB

// ============================================================
// GEMM A: C[M,N] = A[M,K] @ B[K,N] (+bias), 128x128 tiles,
// BK=8, 256 threads, 8x8 microtile (split 4+4 to avoid LDS conflicts)
// Requires M%128==0, N%128==0, K%8==0.
// ============================================================
__global__ __launch_bounds__(256) void gemm128(
    const float* __restrict__ A, const float* __restrict__ B,
    const float* __restrict__ bias, float* __restrict__ C,
    int M, int N, int K)
{
    __shared__ __align__(16) float As[8][132];   // transposed A tile
    __shared__ __align__(16) float Bs[8][132];

    const int tid = threadIdx.x;
    const int bx = blockIdx.x, by = blockIdx.y;
    const float* Ab = A + (size_t)by * 128 * K;
    const float* Bb = B + (size_t)bx * 128;

    const int arow = tid >> 1, acol = (tid & 1) * 4;   // A: 128 rows x 8 cols
    const int brow = tid >> 5, bcol = (tid & 31) * 4;  // B: 8 rows x 128 cols
    const int tx = tid & 15,   ty = tid >> 4;

    float acc[8][8];
#pragma unroll
    for (int i = 0; i < 8; i++)
#pragma unroll
        for (int j = 0; j < 8; j++) acc[i][j] = 0.f;

    for (int kt = 0; kt < K; kt += 8) {
        float4 av = *(const float4*)(Ab + (size_t)arow * K + kt + acol);
        As[acol + 0][arow] = av.x;
        As[acol + 1][arow] = av.y;
        As[acol + 2][arow] = av.z;
        As[acol + 3][arow] = av.w;
        float4 bv = *(const float4*)(Bb + (size_t)(kt + brow) * N + bcol);
        *(float4*)&Bs[brow][bcol] = bv;
        __syncthreads();

#pragma unroll
        for (int kk = 0; kk < 8; kk++) {
            float a[8], b[8];
            *(float4*)&a[0] = *(float4*)&As[kk][ty * 4];
            *(float4*)&a[4] = *(float4*)&As[kk][64 + ty * 4];
            *(float4*)&b[0] = *(float4*)&Bs[kk][tx * 4];
            *(float4*)&b[4] = *(float4*)&Bs[kk][64 + tx * 4];
#pragma unroll
            for (int i = 0; i < 8; i++)
#pragma unroll
                for (int j = 0; j < 8; j++)
                    acc[i][j] += a[i] * b[j];
        }
        __syncthreads();
    }

    // epilogue
    float bb0[4], bb1[4];
    const int c0 = bx * 128 + tx * 4;
    const int c1 = bx * 128 + 64 + tx * 4;
#pragma unroll
    for (int j = 0; j < 4; j++) {
        bb0[j] = bias ? bias[c0 + j] : 0.f;
        bb1[j] = bias ? bias[c1 + j] : 0.f;
    }
#pragma unroll
    for (int i = 0; i < 8; i++) {
        int grow = (i < 4) ? (ty * 4 + i) : (64 + ty * 4 + i - 4);
        int row = by * 128 + grow;
        float4 o0, o1;
        o0.x = acc[i][0] + bb0[0]; o0.y = acc[i][1] + bb0[1];
        o0.z = acc[i][2] + bb0[2]; o0.w = acc[i][3] + bb0[3];
        o1.x = acc[i][4] + bb1[0]; o1.y = acc[i][5] + bb1[1];
        o1.z = acc[i][6] + bb1[2]; o1.w = acc[i][7] + bb1[3];
        *(float4*)(C + (size_t)row * N + c0) = o0;
        *(float4*)(C + (size_t)row * N + c1) = o1;
    }
}

// ============================================================
// Fused K/V projection: N=128 each, 64x128 tiles for parallelism.
// blockIdx.x selects K (0) or V (1). grid = (2, 64).
// ============================================================
__global__ __launch_bounds__(256) void gemm_kv(
    const float* __restrict__ A,
    const float* __restrict__ Wk, const float* __restrict__ bk,
    const float* __restrict__ Wv, const float* __restrict__ bv,
    float* __restrict__ Ck, float* __restrict__ Cv, int K)
{
    __shared__ __align__(16) float As[8][68];
    __shared__ __align__(16) float Bs[8][132];

    const float* B    = blockIdx.x ? Wv : Wk;
    const float* bias = blockIdx.x ? bv : bk;
    float*       C    = blockIdx.x ? Cv : Ck;
    const int N = 128;

    const int tid = threadIdx.x;
    const int by = blockIdx.y;
    const float* Ab = A + (size_t)by * 64 * K;

    const int arow = tid >> 2, acol = (tid & 3) * 2;   // 64 rows x 8 cols, float2
    const int brow = tid >> 5, bcol = (tid & 31) * 4;
    const int tx = tid & 15,   ty = tid >> 4;

    float acc[4][8];
#pragma unroll
    for (int i = 0; i < 4; i++)
#pragma unroll
        for (int j = 0; j < 8; j++) acc[i][j] = 0.f;

    for (int kt = 0; kt < K; kt += 8) {
        float2 av = *(const float2*)(Ab + (size_t)arow * K + kt + acol);
        As[acol + 0][arow] = av.x;
        As[acol + 1][arow] = av.y;
        float4 bv4 = *(const float4*)(B + (size_t)(kt + brow) * N + bcol);
        *(float4*)&Bs[brow][bcol] = bv4;
        __syncthreads();

#pragma unroll
        for (int kk = 0; kk < 8; kk++) {
            float a[4], b[8];
            *(float4*)&a[0] = *(float4*)&As[kk][ty * 4];
            *(float4*)&b[0] = *(float4*)&Bs[kk][tx * 4];
            *(float4*)&b[4] = *(float4*)&Bs[kk][64 + tx * 4];
#pragma unroll
            for (int i = 0; i < 4; i++)
#pragma unroll
                for (int j = 0; j < 8; j++)
                    acc[i][j] += a[i] * b[j];
        }
        __syncthreads();
    }

    const int c0 = tx * 4, c1 = 64 + tx * 4;
    float bb0[4], bb1[4];
#pragma unroll
    for (int j = 0; j < 4; j++) { bb0[j] = bias[c0 + j]; bb1[j] = bias[c1 + j]; }
#pragma unroll
    for (int i = 0; i < 4; i++) {
        int row = by * 64 + ty * 4 + i;
        float4 o0, o1;
        o0.x = acc[i][0] + bb0[0]; o0.y = acc[i][1] + bb0[1];
        o0.z = acc[i][2] + bb0[2]; o0.w = acc[i][3] + bb0[3];
        o1.x = acc[i][4] + bb1[0]; o1.y = acc[i][5] + bb1[1];
        o1.z = acc[i][6] + bb1[2]; o1.w = acc[i][7] + bb1[3];
        *(float4*)(C + (size_t)row * N + c0) = o0;
        *(float4*)(C + (size_t)row * N + c1) = o1;
    }
}

// ============================================================
// RoPE in place on [MTOT, H*64]. One thread per (t, h, i<32).
// ============================================================
__global__ void rope_kernel(float* __restrict__ X, const int* __restrict__ pos,
                            int H, int total)
{
    int idx = blockIdx.x * blockDim.x + threadIdx.x;
    if (idx >= total) return;
    int i = idx & 31;
    int h = (idx >> 5) % H;
    int t = idx / (32 * H);
    float p = (float)pos[t];
    // inv_freq = 1e6^(-i/32) = exp2(i * -log2(1e6)/32)
    const float cexp = -0.622861517791378f;
    float inv = exp2f((float)i * cexp);
    float ang = p * inv;
    float sn, cs;
    sincosf(ang, &sn, &cs);
    size_t base = (size_t)t * (H * DD) + h * DD + i;
    float x1 = X[base], x2 = X[base + 32];
    X[base]      = x1 * cs - x2 * sn;
    X[base + 32] = x2 * cs + x1 * sn;
}

// ============================================================
// Causal GQA flash attention, fp32.
// grid = (B*HQ, N/32). 256 threads = 8 warps, each warp owns 4 q rows.
// K/V share one smem buffer (keeps static smem < 48KB).
// ============================================================
__global__ __launch_bounds__(256) void attn_kernel(
    const float* __restrict__ Q, const float* __restrict__ K,
    const float* __restrict__ V, float* __restrict__ O)
{
    __shared__ __align__(16) float qs[32][68];
    __shared__ __align__(16) float kvs[64][68];
    __shared__ __align__(16) float ps[8][4][64];

    const int bh = blockIdx.x;
    const int b = bh / HQ, h = bh % HQ;
    // reverse y so heaviest (largest q0) blocks launch first
    const int q0 = ((int)gridDim.y - 1 - (int)blockIdx.y) * 32;
    const int kh = h / (HQ / HKV);
    const int tid = threadIdx.x, warp = tid >> 5, lane = tid & 31;
    const float NEG_INF = __int_as_float(0xff800000);

    const float* Qb = Q + ((size_t)b * NN) * (HQ * DD) + h * DD;
    const float* Kb = K + ((size_t)b * NN) * (HKV * DD) + kh * DD;
    const float* Vb = V + ((size_t)b * NN) * (HKV * DD) + kh * DD;

    // load Q tile: 32 rows x 64 floats
    for (int i = tid; i < 32 * 16; i += 256) {
        int r = i >> 4, d4 = i & 15;
        *(float4*)&qs[r][d4 * 4] =
            *(const float4*)(Qb + (size_t)(q0 + r) * (HQ * DD) + d4 * 4);
    }

    float m[4], l[4], o0[4], o1[4];
#pragma unroll
    for (int r = 0; r < 4; r++) { m[r] = NEG_INF; l[r] = 0.f; o0[r] = 0.f; o1[r] = 0.f; }
    const int row0 = warp * 4;
    const int ktiles = q0 / 64 + 1;

    for (int kt = 0; kt < ktiles; kt++) {
        __syncthreads();           // prior PV done (and Q load on first iter)
        // load K tile
        for (int i = tid; i < 64 * 16; i += 256) {
            int r = i >> 4, d4 = i & 15;
            *(float4*)&kvs[r][d4 * 4] =
                *(const float4*)(Kb + (size_t)(kt * 64 + r) * (HKV * DD) + d4 * 4);
        }
        __syncthreads();

        // scores: each lane handles k-cols (lane, lane+32) for 4 rows
        float s[4][2];
#pragma unroll
        for (int r = 0; r < 4; r++) { s[r][0] = 0.f; s[r][1] = 0.f; }
#pragma unroll
        for (int d4 = 0; d4 < 16; d4++) {
            float4 k0 = *(float4*)&kvs[lane][d4 * 4];
            float4 k1 = *(float4*)&kvs[lane + 32][d4 * 4];
#pragma unroll
            for (int r = 0; r < 4; r++) {
                float4 qv = *(float4*)&qs[row0 + r][d4 * 4];
                s[r][0] += qv.x * k0.x + qv.y * k0.y + qv.z * k0.z + qv.w * k0.w;
                s[r][1] += qv.x * k1.x + qv.y * k1.y + qv.z * k1.z + qv.w * k1.w;
            }
        }

        const bool last = (kt == ktiles - 1);
#pragma unroll
        for (int r = 0; r < 4; r++) {
            int qg = q0 + row0 + r;
            float s0 = s[r][0] * 0.125f;
            float s1 = s[r][1] * 0.125f;
            if (last) {
                if (kt * 64 + lane > qg)      s0 = NEG_INF;
                if (kt * 64 + 32 + lane > qg) s1 = NEG_INF;
            }
            float mx = fmaxf(s0, s1);
#pragma unroll
            for (int off = 16; off; off >>= 1)
                mx = fmaxf(mx, __shfl_xor_sync(0xffffffffu, mx, off));
            float mnew = fmaxf(m[r], mx);
            float alpha = __expf(m[r] - mnew);
            float p0 = __expf(s0 - mnew);
            float p1 = __expf(s1 - mnew);
            float ls = p0 + p1;
#pragma unroll
            for (int off = 16; off; off >>= 1)
                ls += __shfl_xor_sync(0xffffffffu, ls, off);
            l[r] = l[r] * alpha + ls;
            m[r] = mnew;
            o0[r] *= alpha; o1[r] *= alpha;
            ps[warp][r][lane]      = p0;
            ps[warp][r][lane + 32] = p1;
        }
        __syncthreads();           // all warps done reading K

        // load V tile into same buffer
        for (int i = tid; i < 64 * 16; i += 256) {
            int r = i >> 4, d4 = i & 15;
            *(float4*)&kvs[r][d4 * 4] =
                *(const float4*)(Vb + (size_t)(kt * 64 + r) * (HKV * DD) + d4 * 4);
        }
        __syncthreads();

        // PV accumulate: o[d] += sum_j p[j] * V[j][d], d = lane, lane+32
#pragma unroll
        for (int j4 = 0; j4 < 16; j4++) {
            float v0[4], v1[4];
#pragma unroll
            for (int jj = 0; jj < 4; jj++) {
                v0[jj] = kvs[j4 * 4 + jj][lane];
                v1[jj] = kvs[j4 * 4 + jj][lane + 32];
            }
#pragma unroll
            for (int r = 0; r < 4; r++) {
                float4 pv = *(float4*)&ps[warp][r][j4 * 4];
                o0[r] += pv.x * v0[0] + pv.y * v0[1] + pv.z * v0[2] + pv.w * v0[3];
                o1[r] += pv.x * v1[0] + pv.y * v1[1] + pv.z * v1[2] + pv.w * v1[3];
            }
        }
    }

    // epilogue: normalize and store [B,N,HQ,D]
#pragma unroll
    for (int r = 0; r < 4; r++) {
        float inv = 1.0f / (l[r] + 1e-8f);
        size_t base = ((size_t)b * NN + q0 + row0 + r) * (HQ * DD) + h * DD;
        O[base + lane]      = o0[r] * inv;
        O[base + 32 + lane] = o1[r] * inv;
    }
}

// ============================================================
extern "C" void kernel_launch(void* const* d_in, const int* in_sizes, int n_in,
                              void* d_out, int out_size)
{
    const float* hs  = (const float*)d_in[0];
    const int*   pos = (const int*)d_in[1];
    const float* q_w = (const float*)d_in[2];
    const float* q_b = (const float*)d_in[3];
    const float* k_w = (const float*)d_in[4];
    const float* k_b = (const float*)d_in[5];
    const float* v_w = (const float*)d_in[6];
    const float* v_b = (const float*)d_in[7];
    const float* o_w = (const float*)d_in[8];
    float* out = (float*)d_out;

    float *pq, *pk, *pv, *po;
    cudaGetSymbolAddress((void**)&pq, g_q);
    cudaGetSymbolAddress((void**)&pk, g_k);
    cudaGetSymbolAddress((void**)&pv, g_v);
    cudaGetSymbolAddress((void**)&po, g_o);

    // Q projection: [4096,896] @ [896,896] + b
    gemm128<<<dim3(7, 32), 256>>>(hs, q_w, q_b, pq, MTOT, HQ * DD, HID);
    // K,V projections fused: [4096,896] @ [896,128] + b, each
    gemm_kv<<<dim3(2, 64), 256>>>(hs, k_w, k_b, v_w, v_b, pk, pv, HID);
    // RoPE on Q and K
    {
        int totq = MTOT * HQ * 32;
        rope_kernel<<<(totq + 255) / 256, 256>>>(pq, pos, HQ, totq);
        int totk = MTOT * HKV * 32;
        rope_kernel<<<(totk + 255) / 256, 256>>>(pk, pos, HKV, totk);
    }
    // causal GQA attention
    attn_kernel<<<dim3(BB * HQ, NN / 32), 256>>>(pq, pk, pv, po);
    // output projection: [4096,896] @ [896,896]
    gemm128<<<dim3(7, 32), 256>>>(po, o_w, nullptr, out, MTOT, HID, HQ * DD);
}

// round 2
// speedup vs baseline: 2.3609x; 2.3609x over previous
#include <cuda_runtime.h>
#include <math.h>

#define BB   2
#define NN   2048
#define HID  896
#define HQ   14
#define HKV  2
#define DD   64
#define MTOT (BB*NN)          // 4096 tokens

// ---- scratch (device globals: no allocations allowed) ----
__device__ float g_q[MTOT*HQ*DD];    // [B,N,HQ,D]
__device__ float g_k[MTOT*HKV*DD];   // [B,N,HKV,D]
__device__ float g_v[MTOT*HKV*DD];
__device__ float g_o[MTOT*HQ*DD];    // attention out

// ============================================================
// helpers
// ============================================================
__device__ __forceinline__ unsigned f2tf32(float f) {
    unsigned u;
    asm("cvt.rna.tf32.f32 %0, %1;" : "=r"(u) : "f"(f));
    return u;
}
__device__ __forceinline__ float ex2f(float x) {
    float y;
    asm("ex2.approx.ftz.f32 %0, %1;" : "=f"(y) : "f"(x));
    return y;
}
__device__ __forceinline__ void mma_tf32(float c[4],
    unsigned a0, unsigned a1, unsigned a2, unsigned a3,
    unsigned b0, unsigned b1)
{
    asm volatile(
        "mma.sync.aligned.m16n8k8.row.col.f32.tf32.tf32.f32 "
        "{%0,%1,%2,%3}, {%4,%5,%6,%7}, {%8,%9}, {%0,%1,%2,%3};\n"
        : "+f"(c[0]), "+f"(c[1]), "+f"(c[2]), "+f"(c[3])
        : "r"(a0), "r"(a1), "r"(a2), "r"(a3), "r"(b0), "r"(b1));
}

// ============================================================
// tf32 tensor-core GEMM: C[M,N] = A[M,K] @ B[K,N] (+bias)
// 128x128x32 tiles, 256 threads = 8 warps in 2x4, warp tile 64x32.
// M%128==0, N%128==0, K%32==0.
// ============================================================
__global__ __launch_bounds__(256) void gemm_tf32(
    const float* __restrict__ A, const float* __restrict__ B,
    const float* __restrict__ bias, float* __restrict__ C,
    int M, int N, int K)
{
    __shared__ unsigned As[128][36];   // bank = (4*row + k) % 32 : conflict-free
    __shared__ unsigned Bs[32][136];   // bank = (8*k + col) % 32 : conflict-free

    const int tid = threadIdx.x;
    const int lane = tid & 31;
    const int warp = tid >> 5;
    const int warpM = warp >> 2;      // 0..1
    const int warpN = warp & 3;       // 0..3
    const int bx = blockIdx.x, by = blockIdx.y;

    const float* Ab = A + (size_t)by * 128 * K;
    const float* Bb = B + (size_t)bx * 128;

    // A load mapping: row = tid>>1, cols (tid&1)*16 + {0,4,8,12}
    const int a_row = tid >> 1, a_c0 = (tid & 1) * 16;
    // B load mapping: row = tid>>3, cols (tid&7)*16 + {0,4,8,12}
    const int b_row = tid >> 3, b_c0 = (tid & 7) * 16;

    float acc[4][4][4];
#pragma unroll
    for (int mf = 0; mf < 4; mf++)
#pragma unroll
        for (int nf = 0; nf < 4; nf++)
#pragma unroll
            for (int i = 0; i < 4; i++) acc[mf][nf][i] = 0.f;

    const int qrow = lane >> 2, qk = lane & 3;

    for (int kt = 0; kt < K; kt += 32) {
#pragma unroll
        for (int v = 0; v < 4; v++) {
            float4 av = *(const float4*)(Ab + (size_t)a_row * K + kt + a_c0 + v * 4);
            As[a_row][a_c0 + v * 4 + 0] = f2tf32(av.x);
            As[a_row][a_c0 + v * 4 + 1] = f2tf32(av.y);
            As[a_row][a_c0 + v * 4 + 2] = f2tf32(av.z);
            As[a_row][a_c0 + v * 4 + 3] = f2tf32(av.w);
            float4 bv = *(const float4*)(Bb + (size_t)(kt + b_row) * N + b_c0 + v * 4);
            Bs[b_row][b_c0 + v * 4 + 0] = f2tf32(bv.x);
            Bs[b_row][b_c0 + v * 4 + 1] = f2tf32(bv.y);
            Bs[b_row][b_c0 + v * 4 + 2] = f2tf32(bv.z);
            Bs[b_row][b_c0 + v * 4 + 3] = f2tf32(bv.w);
        }
        __syncthreads();

#pragma unroll
        for (int ch = 0; ch < 4; ch++) {
            unsigned af[4][4];
#pragma unroll
            for (int mf = 0; mf < 4; mf++) {
                int r = warpM * 64 + mf * 16 + qrow;
                af[mf][0] = As[r][ch * 8 + qk];
                af[mf][1] = As[r + 8][ch * 8 + qk];
                af[mf][2] = As[r][ch * 8 + 4 + qk];
                af[mf][3] = As[r + 8][ch * 8 + 4 + qk];
            }
#pragma unroll
            for (int nf = 0; nf < 4; nf++) {
                int col = warpN * 32 + nf * 8 + qrow;
                unsigned b0 = Bs[ch * 8 + qk][col];
                unsigned b1 = Bs[ch * 8 + 4 + qk][col];
#pragma unroll
                for (int mf = 0; mf < 4; mf++)
                    mma_tf32(acc[mf][nf], af[mf][0], af[mf][1], af[mf][2], af[mf][3], b0, b1);
            }
        }
        __syncthreads();
    }

    // epilogue
#pragma unroll
    for (int nf = 0; nf < 4; nf++) {
        int col = bx * 128 + warpN * 32 + nf * 8 + qk * 2;
        float b0 = bias ? bias[col] : 0.f;
        float b1 = bias ? bias[col + 1] : 0.f;
#pragma unroll
        for (int mf = 0; mf < 4; mf++) {
            int row = by * 128 + warpM * 64 + mf * 16 + qrow;
            float2 o0 = { acc[mf][nf][0] + b0, acc[mf][nf][1] + b1 };
            float2 o1 = { acc[mf][nf][2] + b0, acc[mf][nf][3] + b1 };
            *(float2*)(C + (size_t)row * N + col) = o0;
            *(float2*)(C + (size_t)(row + 8) * N + col) = o1;
        }
    }
}

// ============================================================
// Fused K/V projection (scalar fp32): N=128 each, 64x128 tiles.
// ============================================================
__global__ __launch_bounds__(256) void gemm_kv(
    const float* __restrict__ A,
    const float* __restrict__ Wk, const float* __restrict__ bk,
    const float* __restrict__ Wv, const float* __restrict__ bv,
    float* __restrict__ Ck, float* __restrict__ Cv, int K)
{
    __shared__ __align__(16) float As[8][68];
    __shared__ __align__(16) float Bs[8][132];

    const float* B    = blockIdx.x ? Wv : Wk;
    const float* bias = blockIdx.x ? bv : bk;
    float*       C    = blockIdx.x ? Cv : Ck;
    const int N = 128;

    const int tid = threadIdx.x;
    const int by = blockIdx.y;
    const float* Ab = A + (size_t)by * 64 * K;

    const int arow = tid >> 2, acol = (tid & 3) * 2;
    const int brow = tid >> 5, bcol = (tid & 31) * 4;
    const int tx = tid & 15,   ty = tid >> 4;

    float acc[4][8];
#pragma unroll
    for (int i = 0; i < 4; i++)
#pragma unroll
        for (int j = 0; j < 8; j++) acc[i][j] = 0.f;

    for (int kt = 0; kt < K; kt += 8) {
        float2 av = *(const float2*)(Ab + (size_t)arow * K + kt + acol);
        As[acol + 0][arow] = av.x;
        As[acol + 1][arow] = av.y;
        float4 bv4 = *(const float4*)(B + (size_t)(kt + brow) * N + bcol);
        *(float4*)&Bs[brow][bcol] = bv4;
        __syncthreads();

#pragma unroll
        for (int kk = 0; kk < 8; kk++) {
            float a[4], b[8];
            *(float4*)&a[0] = *(float4*)&As[kk][ty * 4];
            *(float4*)&b[0] = *(float4*)&Bs[kk][tx * 4];
            *(float4*)&b[4] = *(float4*)&Bs[kk][64 + tx * 4];
#pragma unroll
            for (int i = 0; i < 4; i++)
#pragma unroll
                for (int j = 0; j < 8; j++)
                    acc[i][j] += a[i] * b[j];
        }
        __syncthreads();
    }

    const int c0 = tx * 4, c1 = 64 + tx * 4;
    float bb0[4], bb1[4];
#pragma unroll
    for (int j = 0; j < 4; j++) { bb0[j] = bias[c0 + j]; bb1[j] = bias[c1 + j]; }
#pragma unroll
    for (int i = 0; i < 4; i++) {
        int row = by * 64 + ty * 4 + i;
        float4 o0, o1;
        o0.x = acc[i][0] + bb0[0]; o0.y = acc[i][1] + bb0[1];
        o0.z = acc[i][2] + bb0[2]; o0.w = acc[i][3] + bb0[3];
        o1.x = acc[i][4] + bb1[0]; o1.y = acc[i][5] + bb1[1];
        o1.z = acc[i][6] + bb1[2]; o1.w = acc[i][7] + bb1[3];
        *(float4*)(C + (size_t)row * N + c0) = o0;
        *(float4*)(C + (size_t)row * N + c1) = o1;
    }
}

// ============================================================
// RoPE in place on [MTOT, H*64].
// ============================================================
__global__ void rope_kernel(float* __restrict__ X, const int* __restrict__ pos,
                            int H, int total)
{
    int idx = blockIdx.x * blockDim.x + threadIdx.x;
    if (idx >= total) return;
    int i = idx & 31;
    int h = (idx >> 5) % H;
    int t = idx / (32 * H);
    float p = (float)pos[t];
    const float cexp = -0.622861517791378f;  // -log2(1e6)/32
    float inv = exp2f((float)i * cexp);
    float ang = p * inv;
    float sn, cs;
    sincosf(ang, &sn, &cs);
    size_t base = (size_t)t * (H * DD) + h * DD + i;
    float x1 = X[base], x2 = X[base + 32];
    X[base]      = x1 * cs - x2 * sn;
    X[base + 32] = x2 * cs + x1 * sn;
}

// ============================================================
// Causal GQA flash attention, tf32 mma.sync.
// Block: one (b,h), q-tile of 128 rows. 256 threads = 8 warps x 16 rows.
// grid = (B*HQ, NN/128).
// ============================================================
__global__ __launch_bounds__(256) void attn_mma(
    const float* __restrict__ Q, const float* __restrict__ K,
    const float* __restrict__ V, float* __restrict__ O)
{
    __shared__ unsigned ks[64][68];   // [key][d] bank=(4*key+d)%32 for K B-frags
    __shared__ unsigned vs[64][72];   // [key][d] bank=(8*key+d)%32 for V B-frags

    const int bh = blockIdx.x;
    const int b = bh / HQ, h = bh % HQ;
    const int q0 = ((int)gridDim.y - 1 - (int)blockIdx.y) * 128;  // heavy first
    const int kh = h / (HQ / HKV);
    const int tid = threadIdx.x, warp = tid >> 5, lane = tid & 31;
    const int qrow = lane >> 2, qk = lane & 3;
    const float QSCALE = 0.125f * 1.44269504f;  // scale * log2(e)

    const float* Kb = K + ((size_t)b * NN) * (HKV * DD) + kh * DD;
    const float* Vb = V + ((size_t)b * NN) * (HKV * DD) + kh * DD;

    // --- Q fragments in registers (rows q0 + warp*16 + qrow, +8) ---
    unsigned qa[8][4];
    {
        const int r0 = q0 + warp * 16 + qrow;
        const float* qp0 = Q + ((size_t)b * NN + r0) * (HQ * DD) + h * DD;
        const float* qp1 = qp0 + (size_t)8 * (HQ * DD);
#pragma unroll
        for (int ch = 0; ch < 8; ch++) {
            qa[ch][0] = f2tf32(qp0[ch * 8 + qk] * QSCALE);
            qa[ch][1] = f2tf32(qp1[ch * 8 + qk] * QSCALE);
            qa[ch][2] = f2tf32(qp0[ch * 8 + 4 + qk] * QSCALE);
            qa[ch][3] = f2tf32(qp1[ch * 8 + 4 + qk] * QSCALE);
        }
    }

    float o[8][4];
#pragma unroll
    for (int nf = 0; nf < 8; nf++)
#pragma unroll
        for (int i = 0; i < 4; i++) o[nf][i] = 0.f;
    float m0 = -1e30f, m1 = -1e30f, l0 = 0.f, l1 = 0.f;

    const int r0g = q0 + warp * 16 + qrow;   // this thread's global rows
    const int r1g = r0g + 8;
    const int warp_rmax = q0 + warp * 16 + 15;
    const int ktiles = q0 / 64 + 2;
    const int kt_diag = q0 / 64;
    const int srcA = (lane & ~3) | (qk >> 1);
    const int srcB = srcA | 2;

    for (int kt = 0; kt < ktiles; kt++) {
        // load K and V tiles (256 threads, 1024 float4 each)
#pragma unroll
        for (int t = 0; t < 4; t++) {
            int i = tid + t * 256;
            int r = i >> 4, c4 = (i & 15) * 4;
            float4 kv = *(const float4*)(Kb + (size_t)(kt * 64 + r) * (HKV * DD) + c4);
            ks[r][c4 + 0] = f2tf32(kv.x); ks[r][c4 + 1] = f2tf32(kv.y);
            ks[r][c4 + 2] = f2tf32(kv.z); ks[r][c4 + 3] = f2tf32(kv.w);
            float4 vv = *(const float4*)(Vb + (size_t)(kt * 64 + r) * (HKV * DD) + c4);
            vs[r][c4 + 0] = f2tf32(vv.x); vs[r][c4 + 1] = f2tf32(vv.y);
            vs[r][c4 + 2] = f2tf32(vv.z); vs[r][c4 + 3] = f2tf32(vv.w);
        }
        __syncthreads();

        if (kt * 64 <= warp_rmax) {  // warp has at least one visible key
            // ---- S = Q @ K^T (log2-scaled) ----
            float sc[8][4];
#pragma unroll
            for (int nf = 0; nf < 8; nf++)
#pragma unroll
                for (int i = 0; i < 4; i++) sc[nf][i] = 0.f;
#pragma unroll
            for (int ch = 0; ch < 8; ch++) {
#pragma unroll
                for (int nf = 0; nf < 8; nf++) {
                    unsigned b0 = ks[nf * 8 + qrow][ch * 8 + qk];
                    unsigned b1 = ks[nf * 8 + qrow][ch * 8 + 4 + qk];
                    mma_tf32(sc[nf], qa[ch][0], qa[ch][1], qa[ch][2], qa[ch][3], b0, b1);
                }
            }

            // ---- causal mask ----
            if (kt >= kt_diag) {
#pragma unroll
                for (int nf = 0; nf < 8; nf++) {
                    int c = kt * 64 + nf * 8 + qk * 2;
                    if (c > r0g)     sc[nf][0] = -1e30f;
                    if (c + 1 > r0g) sc[nf][1] = -1e30f;
                    if (c > r1g)     sc[nf][2] = -1e30f;
                    if (c + 1 > r1g) sc[nf][3] = -1e30f;
                }
            }

            // ---- online softmax (log2 domain) ----
            float mx0 = -1e30f, mx1 = -1e30f;
#pragma unroll
            for (int nf = 0; nf < 8; nf++) {
                mx0 = fmaxf(mx0, fmaxf(sc[nf][0], sc[nf][1]));
                mx1 = fmaxf(mx1, fmaxf(sc[nf][2], sc[nf][3]));
            }
            mx0 = fmaxf(mx0, __shfl_xor_sync(0xffffffffu, mx0, 1));
            mx0 = fmaxf(mx0, __shfl_xor_sync(0xffffffffu, mx0, 2));
            mx1 = fmaxf(mx1, __shfl_xor_sync(0xffffffffu, mx1, 1));
            mx1 = fmaxf(mx1, __shfl_xor_sync(0xffffffffu, mx1, 2));
            float mn0 = fmaxf(m0, mx0), mn1 = fmaxf(m1, mx1);
            float al0 = ex2f(m0 - mn0), al1 = ex2f(m1 - mn1);
            float s0 = 0.f, s1 = 0.f;
#pragma unroll
            for (int nf = 0; nf < 8; nf++) {
                sc[nf][0] = ex2f(sc[nf][0] - mn0);
                sc[nf][1] = ex2f(sc[nf][1] - mn0);
                sc[nf][2] = ex2f(sc[nf][2] - mn1);
                sc[nf][3] = ex2f(sc[nf][3] - mn1);
                s0 += sc[nf][0] + sc[nf][1];
                s1 += sc[nf][2] + sc[nf][3];
            }
            s0 += __shfl_xor_sync(0xffffffffu, s0, 1);
            s0 += __shfl_xor_sync(0xffffffffu, s0, 2);
            s1 += __shfl_xor_sync(0xffffffffu, s1, 1);
            s1 += __shfl_xor_sync(0xffffffffu, s1, 2);
            l0 = l0 * al0 + s0;  m0 = mn0;
            l1 = l1 * al1 + s1;  m1 = mn1;
#pragma unroll
            for (int nf = 0; nf < 8; nf++) {
                o[nf][0] *= al0; o[nf][1] *= al0;
                o[nf][2] *= al1; o[nf][3] *= al1;
            }

            // ---- O += P @ V ----
#pragma unroll
            for (int jk = 0; jk < 8; jk++) {
                // convert P C-frag (rows r, r+8; cols 2qk,2qk+1) to A-frag
                float c0A = __shfl_sync(0xffffffffu, sc[jk][0], srcA);
                float c1A = __shfl_sync(0xffffffffu, sc[jk][1], srcA);
                float c0B = __shfl_sync(0xffffffffu, sc[jk][0], srcB);
                float c1B = __shfl_sync(0xffffffffu, sc[jk][1], srcB);
                float c2A = __shfl_sync(0xffffffffu, sc[jk][2], srcA);
                float c3A = __shfl_sync(0xffffffffu, sc[jk][3], srcA);
                float c2B = __shfl_sync(0xffffffffu, sc[jk][2], srcB);
                float c3B = __shfl_sync(0xffffffffu, sc[jk][3], srcB);
                bool odd = qk & 1;
                unsigned a0 = f2tf32(odd ? c1A : c0A);
                unsigned a1 = f2tf32(odd ? c3A : c2A);
                unsigned a2 = f2tf32(odd ? c1B : c0B);
                unsigned a3 = f2tf32(odd ? c3B : c2B);
#pragma unroll
                for (int jn = 0; jn < 8; jn++) {
                    unsigned b0 = vs[jk * 8 + qk][jn * 8 + qrow];
                    unsigned b1 = vs[jk * 8 + 4 + qk][jn * 8 + qrow];
                    mma_tf32(o[jn], a0, a1, a2, a3, b0, b1);
                }
            }
        }
        __syncthreads();
    }

    // ---- normalize + store [B,N,HQ,D] ----
    float inv0 = 1.0f / (l0 + 1e-8f);
    float inv1 = 1.0f / (l1 + 1e-8f);
    float* op0 = O + ((size_t)b * NN + r0g) * (HQ * DD) + h * DD;
    float* op1 = O + ((size_t)b * NN + r1g) * (HQ * DD) + h * DD;
#pragma unroll
    for (int nf = 0; nf < 8; nf++) {
        int d = nf * 8 + qk * 2;
        float2 w0 = { o[nf][0] * inv0, o[nf][1] * inv0 };
        float2 w1 = { o[nf][2] * inv1, o[nf][3] * inv1 };
        *(float2*)(op0 + d) = w0;
        *(float2*)(op1 + d) = w1;
    }
}

// ============================================================
extern "C" void kernel_launch(void* const* d_in, const int* in_sizes, int n_in,
                              void* d_out, int out_size)
{
    const float* hs  = (const float*)d_in[0];
    const int*   pos = (const int*)d_in[1];
    const float* q_w = (const float*)d_in[2];
    const float* q_b = (const float*)d_in[3];
    const float* k_w = (const float*)d_in[4];
    const float* k_b = (const float*)d_in[5];
    const float* v_w = (const float*)d_in[6];
    const float* v_b = (const float*)d_in[7];
    const float* o_w = (const float*)d_in[8];
    float* out = (float*)d_out;

    float *pq, *pk, *pv, *po;
    cudaGetSymbolAddress((void**)&pq, g_q);
    cudaGetSymbolAddress((void**)&pk, g_k);
    cudaGetSymbolAddress((void**)&pv, g_v);
    cudaGetSymbolAddress((void**)&po, g_o);

    // Q projection: [4096,896] @ [896,896] + b  (tf32 tensor cores)
    gemm_tf32<<<dim3(7, 32), 256>>>(hs, q_w, q_b, pq, MTOT, HQ * DD, HID);
    // K,V projections: [4096,896] @ [896,128] + b, each (scalar)
    gemm_kv<<<dim3(2, 64), 256>>>(hs, k_w, k_b, v_w, v_b, pk, pv, HID);
    // RoPE on Q and K
    {
        int totq = MTOT * HQ * 32;
        rope_kernel<<<(totq + 255) / 256, 256>>>(pq, pos, HQ, totq);
        int totk = MTOT * HKV * 32;
        rope_kernel<<<(totk + 255) / 256, 256>>>(pk, pos, HKV, totk);
    }
    // causal GQA attention (tf32 tensor cores)
    attn_mma<<<dim3(BB * HQ, NN / 128), 256>>>(pq, pk, pv, po);
    // output projection: [4096,896] @ [896,896]  (tf32 tensor cores)
    gemm_tf32<<<dim3(7, 32), 256>>>(po, o_w, nullptr, out, MTOT, HID, HQ * DD);
}

// round 3
// speedup vs baseline: 2.6668x; 1.1296x over previous
#include <cuda_runtime.h>
#include <math.h>

#define BB   2
#define NN   2048
#define HID  896
#define HQ   14
#define HKV  2
#define DD   64
#define MTOT (BB*NN)          // 4096 tokens

// ---- scratch (device globals: no allocations allowed) ----
__device__ float g_q[MTOT*HQ*DD];    // [B,N,HQ,D]
__device__ float g_k[MTOT*HKV*DD];   // [B,N,HKV,D]
__device__ float g_v[MTOT*HKV*DD];
__device__ float g_o[MTOT*HQ*DD];    // attention out

// ============================================================
// helpers
// ============================================================
__device__ __forceinline__ unsigned f2tf32(float f) {
    unsigned u;
    asm("cvt.rna.tf32.f32 %0, %1;" : "=r"(u) : "f"(f));
    return u;
}
__device__ __forceinline__ float ex2f(float x) {
    float y;
    asm("ex2.approx.ftz.f32 %0, %1;" : "=f"(y) : "f"(x));
    return y;
}
__device__ __forceinline__ void mma_tf32(float c[4],
    unsigned a0, unsigned a1, unsigned a2, unsigned a3,
    unsigned b0, unsigned b1)
{
    asm volatile(
        "mma.sync.aligned.m16n8k8.row.col.f32.tf32.tf32.f32 "
        "{%0,%1,%2,%3}, {%4,%5,%6,%7}, {%8,%9}, {%0,%1,%2,%3};\n"
        : "+f"(c[0]), "+f"(c[1]), "+f"(c[2]), "+f"(c[3])
        : "r"(a0), "r"(a1), "r"(a2), "r"(a3), "r"(b0), "r"(b1));
}
__device__ __forceinline__ void cp_async16(void* sdst, const void* gsrc) {
    unsigned sa = (unsigned)__cvta_generic_to_shared(sdst);
    asm volatile("cp.async.cg.shared.global [%0], [%1], 16;\n"
                 :: "r"(sa), "l"(gsrc));
}
__device__ __forceinline__ void cp_commit() {
    asm volatile("cp.async.commit_group;\n");
}
__device__ __forceinline__ void cp_wait0() {
    asm volatile("cp.async.wait_group 0;\n");
}

// ============================================================
// tf32 GEMM core: C[., N] tile (128x128) at (bx, by).
// cp.async double-buffered, 256 threads = 8 warps (2x4), warp 64x32.
// Dynamic smem: As[2][128][36] + Bs[2][32][136] floats = 71680 B.
// ============================================================
__device__ __forceinline__ void gemm_core(
    const float* __restrict__ A, const float* __restrict__ B,
    const float* __restrict__ bias, float* __restrict__ C,
    int N, int K, int bx, int by)
{
    extern __shared__ char dynsm[];
    float (*As)[128][36]  = reinterpret_cast<float(*)[128][36]>(dynsm);
    float (*Bs)[32][136]  = reinterpret_cast<float(*)[32][136]>(dynsm + 2*128*36*4);

    const int tid = threadIdx.x;
    const int lane = tid & 31;
    const int warp = tid >> 5;
    const int warpM = warp >> 2;
    const int warpN = warp & 3;

    const float* Ab = A + (size_t)by * 128 * K;
    const float* Bb = B + (size_t)bx * 128;

    const int a_row = tid >> 1, a_c0 = (tid & 1) * 16;
    const int b_row = tid >> 3, b_c0 = (tid & 7) * 16;
    const int qrow = lane >> 2, qk = lane & 3;

    float acc[4][4][4];
#pragma unroll
    for (int mf = 0; mf < 4; mf++)
#pragma unroll
        for (int nf = 0; nf < 4; nf++)
#pragma unroll
            for (int i = 0; i < 4; i++) acc[mf][nf][i] = 0.f;

    const int NKT = K / 32;

    // prologue: load tile 0 into buffer 0
#pragma unroll
    for (int v = 0; v < 4; v++) {
        cp_async16(&As[0][a_row][a_c0 + v * 4], Ab + (size_t)a_row * K + a_c0 + v * 4);
        cp_async16(&Bs[0][b_row][b_c0 + v * 4], Bb + (size_t)b_row * N + b_c0 + v * 4);
    }
    cp_commit();

    for (int kt = 0; kt < NKT; kt++) {
        cp_wait0();
        __syncthreads();
        const int cur = kt & 1;
        if (kt + 1 < NKT) {
            const int kofs = (kt + 1) * 32;
#pragma unroll
            for (int v = 0; v < 4; v++) {
                cp_async16(&As[cur ^ 1][a_row][a_c0 + v * 4],
                           Ab + (size_t)a_row * K + kofs + a_c0 + v * 4);
                cp_async16(&Bs[cur ^ 1][b_row][b_c0 + v * 4],
                           Bb + (size_t)(kofs + b_row) * N + b_c0 + v * 4);
            }
        }
        cp_commit();

#pragma unroll
        for (int ch = 0; ch < 4; ch++) {
            unsigned af[4][4];
#pragma unroll
            for (int mf = 0; mf < 4; mf++) {
                int r = warpM * 64 + mf * 16 + qrow;
                af[mf][0] = f2tf32(As[cur][r][ch * 8 + qk]);
                af[mf][1] = f2tf32(As[cur][r + 8][ch * 8 + qk]);
                af[mf][2] = f2tf32(As[cur][r][ch * 8 + 4 + qk]);
                af[mf][3] = f2tf32(As[cur][r + 8][ch * 8 + 4 + qk]);
            }
#pragma unroll
            for (int nf = 0; nf < 4; nf++) {
                int col = warpN * 32 + nf * 8 + qrow;
                unsigned b0 = f2tf32(Bs[cur][ch * 8 + qk][col]);
                unsigned b1 = f2tf32(Bs[cur][ch * 8 + 4 + qk][col]);
#pragma unroll
                for (int mf = 0; mf < 4; mf++)
                    mma_tf32(acc[mf][nf], af[mf][0], af[mf][1], af[mf][2], af[mf][3], b0, b1);
            }
        }
    }

    // epilogue
#pragma unroll
    for (int nf = 0; nf < 4; nf++) {
        int col = bx * 128 + warpN * 32 + nf * 8 + qk * 2;
        float b0 = bias ? bias[col] : 0.f;
        float b1 = bias ? bias[col + 1] : 0.f;
#pragma unroll
        for (int mf = 0; mf < 4; mf++) {
            int row = by * 128 + warpM * 64 + mf * 16 + qrow;
            float2 o0 = { acc[mf][nf][0] + b0, acc[mf][nf][1] + b1 };
            float2 o1 = { acc[mf][nf][2] + b0, acc[mf][nf][3] + b1 };
            *(float2*)(C + (size_t)row * N + col) = o0;
            *(float2*)(C + (size_t)(row + 8) * N + col) = o1;
        }
    }
}

__global__ __launch_bounds__(256, 1) void gemm_tf32(
    const float* __restrict__ A, const float* __restrict__ B,
    const float* __restrict__ bias, float* __restrict__ C,
    int N, int K)
{
    gemm_core(A, B, bias, C, N, K, blockIdx.x, blockIdx.y);
}

__global__ __launch_bounds__(256, 1) void gemm_kv_tf32(
    const float* __restrict__ A,
    const float* __restrict__ Wk, const float* __restrict__ bk, float* __restrict__ Ck,
    const float* __restrict__ Wv, const float* __restrict__ bv, float* __restrict__ Cv,
    int K)
{
    if (blockIdx.z == 0)
        gemm_core(A, Wk, bk, Ck, 128, K, 0, blockIdx.y);
    else
        gemm_core(A, Wv, bv, Cv, 128, K, 0, blockIdx.y);
}

// ============================================================
// RoPE in place on Q and K in one launch.
// ============================================================
__global__ void rope_both(float* __restrict__ Xq, float* __restrict__ Xk,
                          const int* __restrict__ pos)
{
    const int totq = MTOT * HQ * 32;
    const int totk = MTOT * HKV * 32;
    int idx = blockIdx.x * blockDim.x + threadIdx.x;
    float* X;
    int H;
    if (idx < totq) { X = Xq; H = HQ; }
    else if (idx < totq + totk) { X = Xk; H = HKV; idx -= totq; }
    else return;
    int i = idx & 31;
    int h = (idx >> 5) % H;
    int t = idx / (32 * H);
    float p = (float)pos[t];
    const float cexp = -0.622861517791378f;  // -log2(1e6)/32
    float inv = exp2f((float)i * cexp);
    float ang = p * inv;
    float sn, cs;
    sincosf(ang, &sn, &cs);
    size_t base = (size_t)t * (H * DD) + h * DD + i;
    float x1 = X[base], x2 = X[base + 32];
    X[base]      = x1 * cs - x2 * sn;
    X[base + 32] = x2 * cs + x1 * sn;
}

// ============================================================
// Causal GQA flash attention, tf32 mma.sync + cp.async pipeline.
// Block: one (b,h), q-tile 128 rows. 256 threads = 8 warps x 16 rows.
// Dynamic smem: ks[2][64][68] + vs[2][64][72] floats = 71680 B.
// ============================================================
__global__ __launch_bounds__(256, 1) void attn_mma(
    const float* __restrict__ Q, const float* __restrict__ K,
    const float* __restrict__ V, float* __restrict__ O)
{
    extern __shared__ char dynsm[];
    float (*ks)[64][68] = reinterpret_cast<float(*)[64][68]>(dynsm);
    float (*vs)[64][72] = reinterpret_cast<float(*)[64][72]>(dynsm + 2*64*68*4);

    const int bh = blockIdx.x;
    const int b = bh / HQ, h = bh % HQ;
    const int q0 = ((int)gridDim.y - 1 - (int)blockIdx.y) * 128;  // heavy first
    const int kh = h / (HQ / HKV);
    const int tid = threadIdx.x, warp = tid >> 5, lane = tid & 31;
    const int qrow = lane >> 2, qk = lane & 3;
    const float QSCALE = 0.125f * 1.44269504f;  // scale * log2(e)

    const float* Kb = K + ((size_t)b * NN) * (HKV * DD) + kh * DD;
    const float* Vb = V + ((size_t)b * NN) * (HKV * DD) + kh * DD;

    const int ld_r = tid >> 4, ld_c = (tid & 15) * 4;  // 16 rows per pass, 4 passes

    // prologue: tile 0 into buffer 0
#pragma unroll
    for (int t = 0; t < 4; t++) {
        int r = ld_r + t * 16;
        cp_async16(&ks[0][r][ld_c], Kb + (size_t)r * (HKV * DD) + ld_c);
        cp_async16(&vs[0][r][ld_c], Vb + (size_t)r * (HKV * DD) + ld_c);
    }
    cp_commit();

    // --- Q fragments in registers ---
    unsigned qa[8][4];
    {
        const int r0 = q0 + warp * 16 + qrow;
        const float* qp0 = Q + ((size_t)b * NN + r0) * (HQ * DD) + h * DD;
        const float* qp1 = qp0 + (size_t)8 * (HQ * DD);
#pragma unroll
        for (int ch = 0; ch < 8; ch++) {
            qa[ch][0] = f2tf32(qp0[ch * 8 + qk] * QSCALE);
            qa[ch][1] = f2tf32(qp1[ch * 8 + qk] * QSCALE);
            qa[ch][2] = f2tf32(qp0[ch * 8 + 4 + qk] * QSCALE);
            qa[ch][3] = f2tf32(qp1[ch * 8 + 4 + qk] * QSCALE);
        }
    }

    float o[8][4];
#pragma unroll
    for (int nf = 0; nf < 8; nf++)
#pragma unroll
        for (int i = 0; i < 4; i++) o[nf][i] = 0.f;
    float m0 = -1e30f, m1 = -1e30f, l0 = 0.f, l1 = 0.f;

    const int r0g = q0 + warp * 16 + qrow;
    const int r1g = r0g + 8;
    const int warp_rmax = q0 + warp * 16 + 15;
    const int ktiles = q0 / 64 + 2;
    const int kt_diag = q0 / 64;
    const int srcA = (lane & ~3) | (qk >> 1);
    const int srcB = srcA | 2;

    for (int kt = 0; kt < ktiles; kt++) {
        cp_wait0();
        __syncthreads();
        const int cur = kt & 1;
        if (kt + 1 < ktiles) {
            const int base = (kt + 1) * 64;
#pragma unroll
            for (int t = 0; t < 4; t++) {
                int r = ld_r + t * 16;
                cp_async16(&ks[cur ^ 1][r][ld_c],
                           Kb + (size_t)(base + r) * (HKV * DD) + ld_c);
                cp_async16(&vs[cur ^ 1][r][ld_c],
                           Vb + (size_t)(base + r) * (HKV * DD) + ld_c);
            }
        }
        cp_commit();

        if (kt * 64 <= warp_rmax) {
            // ---- S = Q @ K^T (log2-scaled) ----
            float sc[8][4];
#pragma unroll
            for (int nf = 0; nf < 8; nf++)
#pragma unroll
                for (int i = 0; i < 4; i++) sc[nf][i] = 0.f;
#pragma unroll
            for (int ch = 0; ch < 8; ch++) {
#pragma unroll
                for (int nf = 0; nf < 8; nf++) {
                    unsigned b0 = f2tf32(ks[cur][nf * 8 + qrow][ch * 8 + qk]);
                    unsigned b1 = f2tf32(ks[cur][nf * 8 + qrow][ch * 8 + 4 + qk]);
                    mma_tf32(sc[nf], qa[ch][0], qa[ch][1], qa[ch][2], qa[ch][3], b0, b1);
                }
            }

            // ---- causal mask ----
            if (kt >= kt_diag) {
#pragma unroll
                for (int nf = 0; nf < 8; nf++) {
                    int c = kt * 64 + nf * 8 + qk * 2;
                    if (c > r0g)     sc[nf][0] = -1e30f;
                    if (c + 1 > r0g) sc[nf][1] = -1e30f;
                    if (c > r1g)     sc[nf][2] = -1e30f;
                    if (c + 1 > r1g) sc[nf][3] = -1e30f;
                }
            }

            // ---- online softmax (log2 domain) ----
            float mx0 = -1e30f, mx1 = -1e30f;
#pragma unroll
            for (int nf = 0; nf < 8; nf++) {
                mx0 = fmaxf(mx0, fmaxf(sc[nf][0], sc[nf][1]));
                mx1 = fmaxf(mx1, fmaxf(sc[nf][2], sc[nf][3]));
            }
            mx0 = fmaxf(mx0, __shfl_xor_sync(0xffffffffu, mx0, 1));
            mx0 = fmaxf(mx0, __shfl_xor_sync(0xffffffffu, mx0, 2));
            mx1 = fmaxf(mx1, __shfl_xor_sync(0xffffffffu, mx1, 1));
            mx1 = fmaxf(mx1, __shfl_xor_sync(0xffffffffu, mx1, 2));
            float mn0 = fmaxf(m0, mx0), mn1 = fmaxf(m1, mx1);
            float al0 = ex2f(m0 - mn0), al1 = ex2f(m1 - mn1);
            float s0 = 0.f, s1 = 0.f;
#pragma unroll
            for (int nf = 0; nf < 8; nf++) {
                sc[nf][0] = ex2f(sc[nf][0] - mn0);
                sc[nf][1] = ex2f(sc[nf][1] - mn0);
                sc[nf][2] = ex2f(sc[nf][2] - mn1);
                sc[nf][3] = ex2f(sc[nf][3] - mn1);
                s0 += sc[nf][0] + sc[nf][1];
                s1 += sc[nf][2] + sc[nf][3];
            }
            s0 += __shfl_xor_sync(0xffffffffu, s0, 1);
            s0 += __shfl_xor_sync(0xffffffffu, s0, 2);
            s1 += __shfl_xor_sync(0xffffffffu, s1, 1);
            s1 += __shfl_xor_sync(0xffffffffu, s1, 2);
            l0 = l0 * al0 + s0;  m0 = mn0;
            l1 = l1 * al1 + s1;  m1 = mn1;
#pragma unroll
            for (int nf = 0; nf < 8; nf++) {
                o[nf][0] *= al0; o[nf][1] *= al0;
                o[nf][2] *= al1; o[nf][3] *= al1;
            }

            // ---- O += P @ V ----
#pragma unroll
            for (int jk = 0; jk < 8; jk++) {
                float c0A = __shfl_sync(0xffffffffu, sc[jk][0], srcA);
                float c1A = __shfl_sync(0xffffffffu, sc[jk][1], srcA);
                float c0B = __shfl_sync(0xffffffffu, sc[jk][0], srcB);
                float c1B = __shfl_sync(0xffffffffu, sc[jk][1], srcB);
                float c2A = __shfl_sync(0xffffffffu, sc[jk][2], srcA);
                float c3A = __shfl_sync(0xffffffffu, sc[jk][3], srcA);
                float c2B = __shfl_sync(0xffffffffu, sc[jk][2], srcB);
                float c3B = __shfl_sync(0xffffffffu, sc[jk][3], srcB);
                bool odd = qk & 1;
                unsigned a0 = f2tf32(odd ? c1A : c0A);
                unsigned a1 = f2tf32(odd ? c3A : c2A);
                unsigned a2 = f2tf32(odd ? c1B : c0B);
                unsigned a3 = f2tf32(odd ? c3B : c2B);
#pragma unroll
                for (int jn = 0; jn < 8; jn++) {
                    unsigned b0 = f2tf32(vs[cur][jk * 8 + qk][jn * 8 + qrow]);
                    unsigned b1 = f2tf32(vs[cur][jk * 8 + 4 + qk][jn * 8 + qrow]);
                    mma_tf32(o[jn], a0, a1, a2, a3, b0, b1);
                }
            }
        }
    }

    // ---- normalize + store [B,N,HQ,D] ----
    float inv0 = 1.0f / (l0 + 1e-8f);
    float inv1 = 1.0f / (l1 + 1e-8f);
    float* op0 = O + ((size_t)b * NN + r0g) * (HQ * DD) + h * DD;
    float* op1 = O + ((size_t)b * NN + r1g) * (HQ * DD) + h * DD;
#pragma unroll
    for (int nf = 0; nf < 8; nf++) {
        int d = nf * 8 + qk * 2;
        float2 w0 = { o[nf][0] * inv0, o[nf][1] * inv0 };
        float2 w1 = { o[nf][2] * inv1, o[nf][3] * inv1 };
        *(float2*)(op0 + d) = w0;
        *(float2*)(op1 + d) = w1;
    }
}

// ============================================================
extern "C" void kernel_launch(void* const* d_in, const int* in_sizes, int n_in,
                              void* d_out, int out_size)
{
    const float* hs  = (const float*)d_in[0];
    const int*   pos = (const int*)d_in[1];
    const float* q_w = (const float*)d_in[2];
    const float* q_b = (const float*)d_in[3];
    const float* k_w = (const float*)d_in[4];
    const float* k_b = (const float*)d_in[5];
    const float* v_w = (const float*)d_in[6];
    const float* v_b = (const float*)d_in[7];
    const float* o_w = (const float*)d_in[8];
    float* out = (float*)d_out;

    float *pq, *pk, *pv, *po;
    cudaGetSymbolAddress((void**)&pq, g_q);
    cudaGetSymbolAddress((void**)&pk, g_k);
    cudaGetSymbolAddress((void**)&pv, g_v);
    cudaGetSymbolAddress((void**)&po, g_o);

    const int GEMM_SMEM = 2*128*36*4 + 2*32*136*4;   // 71680
    const int ATTN_SMEM = 2*64*68*4  + 2*64*72*4;    // 71680
    cudaFuncSetAttribute(gemm_tf32,    cudaFuncAttributeMaxDynamicSharedMemorySize, GEMM_SMEM);
    cudaFuncSetAttribute(gemm_kv_tf32, cudaFuncAttributeMaxDynamicSharedMemorySize, GEMM_SMEM);
    cudaFuncSetAttribute(attn_mma,     cudaFuncAttributeMaxDynamicSharedMemorySize, ATTN_SMEM);

    // Q projection: [4096,896] @ [896,896] + b
    gemm_tf32<<<dim3(7, 32), 256, GEMM_SMEM>>>(hs, q_w, q_b, pq, HQ * DD, HID);
    // K,V projections: [4096,896] @ [896,128] + b each, one launch
    gemm_kv_tf32<<<dim3(1, 32, 2), 256, GEMM_SMEM>>>(hs, k_w, k_b, pk, v_w, v_b, pv, HID);
    // RoPE on Q and K (single launch)
    {
        int tot = MTOT * (HQ + HKV) * 32;
        rope_both<<<(tot + 255) / 256, 256>>>(pq, pk, pos);
    }
    // causal GQA attention
    attn_mma<<<dim3(BB * HQ, NN / 128), 256, ATTN_SMEM>>>(pq, pk, pv, po);
    // output projection: [4096,896] @ [896,896]
    gemm_tf32<<<dim3(7, 32), 256, GEMM_SMEM>>>(po, o_w, nullptr, out, HID, HQ * DD);
}

// round 4
// speedup vs baseline: 3.0958x; 1.1609x over previous
#include <cuda_runtime.h>
#include <math.h>

#define BB   2
#define NN   2048
#define HID  896
#define HQ   14
#define HKV  2
#define DD   64
#define MTOT (BB*NN)          // 4096 tokens
#define NQKV 1152             // 896 Q + 128 K + 128 V

// ---- scratch (device globals: no allocations allowed) ----
__device__ float g_qkv[MTOT*NQKV];   // fused QKV proj output, row stride 1152
__device__ float g_o[MTOT*HQ*DD];    // attention out (tf32-rounded)
__device__ float g_hsr[MTOT*HID];    // tf32-rounded hidden_states
__device__ float g_wqkv[HID*NQKV];   // packed+rounded [896][1152] weight
__device__ float g_bqkv[NQKV];       // packed bias
__device__ float g_owr[HID*HID];     // rounded o_w

// ============================================================
// helpers
// ============================================================
__device__ __forceinline__ unsigned f2tf32(float f) {
    unsigned u;
    asm("cvt.rna.tf32.f32 %0, %1;" : "=r"(u) : "f"(f));
    return u;
}
__device__ __forceinline__ float rnd_tf32(float f) {
    return __uint_as_float(f2tf32(f));
}
__device__ __forceinline__ float ex2f(float x) {
    float y;
    asm("ex2.approx.ftz.f32 %0, %1;" : "=f"(y) : "f"(x));
    return y;
}
__device__ __forceinline__ void mma_tf32(float c[4],
    unsigned a0, unsigned a1, unsigned a2, unsigned a3,
    unsigned b0, unsigned b1)
{
    asm volatile(
        "mma.sync.aligned.m16n8k8.row.col.f32.tf32.tf32.f32 "
        "{%0,%1,%2,%3}, {%4,%5,%6,%7}, {%8,%9}, {%0,%1,%2,%3};\n"
        : "+f"(c[0]), "+f"(c[1]), "+f"(c[2]), "+f"(c[3])
        : "r"(a0), "r"(a1), "r"(a2), "r"(a3), "r"(b0), "r"(b1));
}
__device__ __forceinline__ void cp_async16(void* sdst, const void* gsrc) {
    unsigned sa = (unsigned)__cvta_generic_to_shared(sdst);
    asm volatile("cp.async.cg.shared.global [%0], [%1], 16;\n"
                 :: "r"(sa), "l"(gsrc));
}
__device__ __forceinline__ void cp_commit() {
    asm volatile("cp.async.commit_group;\n");
}
__device__ __forceinline__ void cp_wait0() {
    asm volatile("cp.async.wait_group 0;\n");
}

// ============================================================
// prep kernels: round-to-tf32 copies + QKV weight/bias packing
// ============================================================
__global__ void round4_kernel(const float4* __restrict__ src,
                              float4* __restrict__ dst, int n4)
{
    int idx = blockIdx.x * blockDim.x + threadIdx.x;
    if (idx >= n4) return;
    float4 v = src[idx];
    v.x = rnd_tf32(v.x); v.y = rnd_tf32(v.y);
    v.z = rnd_tf32(v.z); v.w = rnd_tf32(v.w);
    dst[idx] = v;
}

__global__ void pack_qkv_kernel(
    const float* __restrict__ qw, const float* __restrict__ kw,
    const float* __restrict__ vw, const float* __restrict__ qb,
    const float* __restrict__ kb, const float* __restrict__ vb,
    float* __restrict__ w, float* __restrict__ bias)
{
    int idx = blockIdx.x * blockDim.x + threadIdx.x;
    const int total = HID * NQKV;
    if (idx < total) {
        int row = idx / NQKV, col = idx % NQKV;
        float v = (col < 896) ? qw[row * 896 + col]
                : (col < 1024) ? kw[row * 128 + (col - 896)]
                               : vw[row * 128 + (col - 1024)];
        w[idx] = rnd_tf32(v);
    }
    if (idx < NQKV) {
        bias[idx] = (idx < 896) ? qb[idx]
                  : (idx < 1024) ? kb[idx - 896] : vb[idx - 1024];
    }
}

// ============================================================
// tf32 GEMM core (inputs pre-rounded -> no cvt in inner loop).
// 128x128x32 tiles, cp.async double-buffered, 8 warps (2x4).
// round_out: round outputs of this block's columns to tf32.
// ============================================================
__device__ __forceinline__ void gemm_core(
    const float* __restrict__ A, const float* __restrict__ B,
    const float* __restrict__ bias, float* __restrict__ C,
    int N, int K, int bx, int by, bool round_out)
{
    extern __shared__ char dynsm[];
    float (*As)[128][36]  = reinterpret_cast<float(*)[128][36]>(dynsm);
    float (*Bs)[32][136]  = reinterpret_cast<float(*)[32][136]>(dynsm + 2*128*36*4);

    const int tid = threadIdx.x;
    const int lane = tid & 31;
    const int warp = tid >> 5;
    const int warpM = warp >> 2;
    const int warpN = warp & 3;

    const float* Ab = A + (size_t)by * 128 * K;
    const float* Bb = B + (size_t)bx * 128;

    const int a_row = tid >> 1, a_c0 = (tid & 1) * 16;
    const int b_row = tid >> 3, b_c0 = (tid & 7) * 16;
    const int qrow = lane >> 2, qk = lane & 3;

    float acc[4][4][4];
#pragma unroll
    for (int mf = 0; mf < 4; mf++)
#pragma unroll
        for (int nf = 0; nf < 4; nf++)
#pragma unroll
            for (int i = 0; i < 4; i++) acc[mf][nf][i] = 0.f;

    const int NKT = K / 32;

#pragma unroll
    for (int v = 0; v < 4; v++) {
        cp_async16(&As[0][a_row][a_c0 + v * 4], Ab + (size_t)a_row * K + a_c0 + v * 4);
        cp_async16(&Bs[0][b_row][b_c0 + v * 4], Bb + (size_t)b_row * N + b_c0 + v * 4);
    }
    cp_commit();

    for (int kt = 0; kt < NKT; kt++) {
        cp_wait0();
        __syncthreads();
        const int cur = kt & 1;
        if (kt + 1 < NKT) {
            const int kofs = (kt + 1) * 32;
#pragma unroll
            for (int v = 0; v < 4; v++) {
                cp_async16(&As[cur ^ 1][a_row][a_c0 + v * 4],
                           Ab + (size_t)a_row * K + kofs + a_c0 + v * 4);
                cp_async16(&Bs[cur ^ 1][b_row][b_c0 + v * 4],
                           Bb + (size_t)(kofs + b_row) * N + b_c0 + v * 4);
            }
        }
        cp_commit();

#pragma unroll
        for (int ch = 0; ch < 4; ch++) {
            unsigned af[4][4];
#pragma unroll
            for (int mf = 0; mf < 4; mf++) {
                int r = warpM * 64 + mf * 16 + qrow;
                af[mf][0] = __float_as_uint(As[cur][r][ch * 8 + qk]);
                af[mf][1] = __float_as_uint(As[cur][r + 8][ch * 8 + qk]);
                af[mf][2] = __float_as_uint(As[cur][r][ch * 8 + 4 + qk]);
                af[mf][3] = __float_as_uint(As[cur][r + 8][ch * 8 + 4 + qk]);
            }
#pragma unroll
            for (int nf = 0; nf < 4; nf++) {
                int col = warpN * 32 + nf * 8 + qrow;
                unsigned b0 = __float_as_uint(Bs[cur][ch * 8 + qk][col]);
                unsigned b1 = __float_as_uint(Bs[cur][ch * 8 + 4 + qk][col]);
#pragma unroll
                for (int mf = 0; mf < 4; mf++)
                    mma_tf32(acc[mf][nf], af[mf][0], af[mf][1], af[mf][2], af[mf][3], b0, b1);
            }
        }
    }

#pragma unroll
    for (int nf = 0; nf < 4; nf++) {
        int col = bx * 128 + warpN * 32 + nf * 8 + qk * 2;
        float b0 = bias ? bias[col] : 0.f;
        float b1 = bias ? bias[col + 1] : 0.f;
#pragma unroll
        for (int mf = 0; mf < 4; mf++) {
            int row = by * 128 + warpM * 64 + mf * 16 + qrow;
            float2 o0 = { acc[mf][nf][0] + b0, acc[mf][nf][1] + b1 };
            float2 o1 = { acc[mf][nf][2] + b0, acc[mf][nf][3] + b1 };
            if (round_out) {
                o0.x = rnd_tf32(o0.x); o0.y = rnd_tf32(o0.y);
                o1.x = rnd_tf32(o1.x); o1.y = rnd_tf32(o1.y);
            }
            *(float2*)(C + (size_t)row * N + col) = o0;
            *(float2*)(C + (size_t)(row + 8) * N + col) = o1;
        }
    }
}

__global__ __launch_bounds__(256, 1) void gemm_tf32(
    const float* __restrict__ A, const float* __restrict__ B,
    const float* __restrict__ bias, float* __restrict__ C,
    int N, int K, int round_from_col)
{
    gemm_core(A, B, bias, C, N, K, blockIdx.x, blockIdx.y,
              (int)blockIdx.x * 128 >= round_from_col);
}

// ============================================================
// RoPE in place on g_qkv (Q cols 0..895, K cols 896..1023).
// K outputs are tf32-rounded (consumed as mma B operand raw).
// ============================================================
__global__ void rope_qkv(float* __restrict__ qkv, const int* __restrict__ pos)
{
    int idx = blockIdx.x * blockDim.x + threadIdx.x;
    const int tot = MTOT * (HQ + HKV) * 32;
    if (idx >= tot) return;
    int i = idx & 31;
    int slot = (idx >> 5) & 15;
    int t = idx >> 9;
    float p = (float)pos[t];
    const float cexp = -0.622861517791378f;  // -log2(1e6)/32
    float inv = exp2f((float)i * cexp);
    float ang = p * inv;
    float sn, cs;
    sincosf(ang, &sn, &cs);
    int col = (slot < HQ) ? slot * DD : 896 + (slot - HQ) * DD;
    size_t base = (size_t)t * NQKV + col + i;
    float x1 = qkv[base], x2 = qkv[base + 32];
    float r1 = x1 * cs - x2 * sn;
    float r2 = x2 * cs + x1 * sn;
    if (slot >= HQ) { r1 = rnd_tf32(r1); r2 = rnd_tf32(r2); }
    qkv[base]      = r1;
    qkv[base + 32] = r2;
}

// ============================================================
// Causal GQA flash attention, tf32 mma.sync + cp.async pipeline.
// K/V pre-rounded -> no cvt in inner loops. Output rounded.
// ============================================================
__global__ __launch_bounds__(256, 1) void attn_mma(
    const float* __restrict__ QKV, float* __restrict__ O)
{
    extern __shared__ char dynsm[];
    float (*ks)[64][68] = reinterpret_cast<float(*)[64][68]>(dynsm);
    float (*vs)[64][72] = reinterpret_cast<float(*)[64][72]>(dynsm + 2*64*68*4);

    const int bh = blockIdx.x;
    const int b = bh / HQ, h = bh % HQ;
    const int q0 = ((int)gridDim.y - 1 - (int)blockIdx.y) * 128;  // heavy first
    const int kh = h / (HQ / HKV);
    const int tid = threadIdx.x, warp = tid >> 5, lane = tid & 31;
    const int qrow = lane >> 2, qk = lane & 3;
    const float QSCALE = 0.125f * 1.44269504f;  // scale * log2(e)

    const float* Kb = QKV + (size_t)(b * NN) * NQKV + 896 + kh * DD;
    const float* Vb = QKV + (size_t)(b * NN) * NQKV + 1024 + kh * DD;

    const int ld_r = tid >> 4, ld_c = (tid & 15) * 4;

#pragma unroll
    for (int t = 0; t < 4; t++) {
        int r = ld_r + t * 16;
        cp_async16(&ks[0][r][ld_c], Kb + (size_t)r * NQKV + ld_c);
        cp_async16(&vs[0][r][ld_c], Vb + (size_t)r * NQKV + ld_c);
    }
    cp_commit();

    // --- Q fragments in registers (cvt once here) ---
    unsigned qa[8][4];
    {
        const int r0 = q0 + warp * 16 + qrow;
        const float* qp0 = QKV + (size_t)(b * NN + r0) * NQKV + h * DD;
        const float* qp1 = qp0 + (size_t)8 * NQKV;
#pragma unroll
        for (int ch = 0; ch < 8; ch++) {
            qa[ch][0] = f2tf32(qp0[ch * 8 + qk] * QSCALE);
            qa[ch][1] = f2tf32(qp1[ch * 8 + qk] * QSCALE);
            qa[ch][2] = f2tf32(qp0[ch * 8 + 4 + qk] * QSCALE);
            qa[ch][3] = f2tf32(qp1[ch * 8 + 4 + qk] * QSCALE);
        }
    }

    float o[8][4];
#pragma unroll
    for (int nf = 0; nf < 8; nf++)
#pragma unroll
        for (int i = 0; i < 4; i++) o[nf][i] = 0.f;
    float m0 = -1e30f, m1 = -1e30f, l0 = 0.f, l1 = 0.f;

    const int r0g = q0 + warp * 16 + qrow;
    const int r1g = r0g + 8;
    const int warp_rmax = q0 + warp * 16 + 15;
    const int ktiles = q0 / 64 + 2;
    const int kt_diag = q0 / 64;
    const int srcA = (lane & ~3) | (qk >> 1);
    const int srcB = srcA | 2;

    for (int kt = 0; kt < ktiles; kt++) {
        cp_wait0();
        __syncthreads();
        const int cur = kt & 1;
        if (kt + 1 < ktiles) {
            const int base = (kt + 1) * 64;
#pragma unroll
            for (int t = 0; t < 4; t++) {
                int r = ld_r + t * 16;
                cp_async16(&ks[cur ^ 1][r][ld_c],
                           Kb + (size_t)(base + r) * NQKV + ld_c);
                cp_async16(&vs[cur ^ 1][r][ld_c],
                           Vb + (size_t)(base + r) * NQKV + ld_c);
            }
        }
        cp_commit();

        if (kt * 64 <= warp_rmax) {
            // ---- S = Q @ K^T (log2-scaled) ----
            float sc[8][4];
#pragma unroll
            for (int nf = 0; nf < 8; nf++)
#pragma unroll
                for (int i = 0; i < 4; i++) sc[nf][i] = 0.f;
#pragma unroll
            for (int ch = 0; ch < 8; ch++) {
#pragma unroll
                for (int nf = 0; nf < 8; nf++) {
                    unsigned b0 = __float_as_uint(ks[cur][nf * 8 + qrow][ch * 8 + qk]);
                    unsigned b1 = __float_as_uint(ks[cur][nf * 8 + qrow][ch * 8 + 4 + qk]);
                    mma_tf32(sc[nf], qa[ch][0], qa[ch][1], qa[ch][2], qa[ch][3], b0, b1);
                }
            }

            // ---- causal mask ----
            if (kt >= kt_diag) {
#pragma unroll
                for (int nf = 0; nf < 8; nf++) {
                    int c = kt * 64 + nf * 8 + qk * 2;
                    if (c > r0g)     sc[nf][0] = -1e30f;
                    if (c + 1 > r0g) sc[nf][1] = -1e30f;
                    if (c > r1g)     sc[nf][2] = -1e30f;
                    if (c + 1 > r1g) sc[nf][3] = -1e30f;
                }
            }

            // ---- online softmax (log2 domain) ----
            float mx0 = -1e30f, mx1 = -1e30f;
#pragma unroll
            for (int nf = 0; nf < 8; nf++) {
                mx0 = fmaxf(mx0, fmaxf(sc[nf][0], sc[nf][1]));
                mx1 = fmaxf(mx1, fmaxf(sc[nf][2], sc[nf][3]));
            }
            mx0 = fmaxf(mx0, __shfl_xor_sync(0xffffffffu, mx0, 1));
            mx0 = fmaxf(mx0, __shfl_xor_sync(0xffffffffu, mx0, 2));
            mx1 = fmaxf(mx1, __shfl_xor_sync(0xffffffffu, mx1, 1));
            mx1 = fmaxf(mx1, __shfl_xor_sync(0xffffffffu, mx1, 2));
            float mn0 = fmaxf(m0, mx0), mn1 = fmaxf(m1, mx1);
            float al0 = ex2f(m0 - mn0), al1 = ex2f(m1 - mn1);
            float s0 = 0.f, s1 = 0.f;
#pragma unroll
            for (int nf = 0; nf < 8; nf++) {
                sc[nf][0] = ex2f(sc[nf][0] - mn0);
                sc[nf][1] = ex2f(sc[nf][1] - mn0);
                sc[nf][2] = ex2f(sc[nf][2] - mn1);
                sc[nf][3] = ex2f(sc[nf][3] - mn1);
                s0 += sc[nf][0] + sc[nf][1];
                s1 += sc[nf][2] + sc[nf][3];
            }
            s0 += __shfl_xor_sync(0xffffffffu, s0, 1);
            s0 += __shfl_xor_sync(0xffffffffu, s0, 2);
            s1 += __shfl_xor_sync(0xffffffffu, s1, 1);
            s1 += __shfl_xor_sync(0xffffffffu, s1, 2);
            l0 = l0 * al0 + s0;  m0 = mn0;
            l1 = l1 * al1 + s1;  m1 = mn1;
#pragma unroll
            for (int nf = 0; nf < 8; nf++) {
                o[nf][0] *= al0; o[nf][1] *= al0;
                o[nf][2] *= al1; o[nf][3] *= al1;
            }

            // ---- O += P @ V ----
#pragma unroll
            for (int jk = 0; jk < 8; jk++) {
                float c0A = __shfl_sync(0xffffffffu, sc[jk][0], srcA);
                float c1A = __shfl_sync(0xffffffffu, sc[jk][1], srcA);
                float c0B = __shfl_sync(0xffffffffu, sc[jk][0], srcB);
                float c1B = __shfl_sync(0xffffffffu, sc[jk][1], srcB);
                float c2A = __shfl_sync(0xffffffffu, sc[jk][2], srcA);
                float c3A = __shfl_sync(0xffffffffu, sc[jk][3], srcA);
                float c2B = __shfl_sync(0xffffffffu, sc[jk][2], srcB);
                float c3B = __shfl_sync(0xffffffffu, sc[jk][3], srcB);
                bool odd = qk & 1;
                unsigned a0 = f2tf32(odd ? c1A : c0A);
                unsigned a1 = f2tf32(odd ? c3A : c2A);
                unsigned a2 = f2tf32(odd ? c1B : c0B);
                unsigned a3 = f2tf32(odd ? c3B : c2B);
#pragma unroll
                for (int jn = 0; jn < 8; jn++) {
                    unsigned b0 = __float_as_uint(vs[cur][jk * 8 + qk][jn * 8 + qrow]);
                    unsigned b1 = __float_as_uint(vs[cur][jk * 8 + 4 + qk][jn * 8 + qrow]);
                    mma_tf32(o[jn], a0, a1, a2, a3, b0, b1);
                }
            }
        }
    }

    // ---- normalize + store rounded (feeds O-proj as pre-rounded A) ----
    float inv0 = 1.0f / (l0 + 1e-8f);
    float inv1 = 1.0f / (l1 + 1e-8f);
    float* op0 = O + (size_t)(b * NN + r0g) * (HQ * DD) + h * DD;
    float* op1 = O + (size_t)(b * NN + r1g) * (HQ * DD) + h * DD;
#pragma unroll
    for (int nf = 0; nf < 8; nf++) {
        int d = nf * 8 + qk * 2;
        float2 w0 = { rnd_tf32(o[nf][0] * inv0), rnd_tf32(o[nf][1] * inv0) };
        float2 w1 = { rnd_tf32(o[nf][2] * inv1), rnd_tf32(o[nf][3] * inv1) };
        *(float2*)(op0 + d) = w0;
        *(float2*)(op1 + d) = w1;
    }
}

// ============================================================
extern "C" void kernel_launch(void* const* d_in, const int* in_sizes, int n_in,
                              void* d_out, int out_size)
{
    const float* hs  = (const float*)d_in[0];
    const int*   pos = (const int*)d_in[1];
    const float* q_w = (const float*)d_in[2];
    const float* q_b = (const float*)d_in[3];
    const float* k_w = (const float*)d_in[4];
    const float* k_b = (const float*)d_in[5];
    const float* v_w = (const float*)d_in[6];
    const float* v_b = (const float*)d_in[7];
    const float* o_w = (const float*)d_in[8];
    float* out = (float*)d_out;

    float *pqkv, *po, *phsr, *pwqkv, *pbqkv, *powr;
    cudaGetSymbolAddress((void**)&pqkv,  g_qkv);
    cudaGetSymbolAddress((void**)&po,    g_o);
    cudaGetSymbolAddress((void**)&phsr,  g_hsr);
    cudaGetSymbolAddress((void**)&pwqkv, g_wqkv);
    cudaGetSymbolAddress((void**)&pbqkv, g_bqkv);
    cudaGetSymbolAddress((void**)&powr,  g_owr);

    const int GEMM_SMEM = 2*128*36*4 + 2*32*136*4;   // 71680
    const int ATTN_SMEM = 2*64*68*4  + 2*64*72*4;    // 71680
    cudaFuncSetAttribute(gemm_tf32, cudaFuncAttributeMaxDynamicSharedMemorySize, GEMM_SMEM);
    cudaFuncSetAttribute(attn_mma,  cudaFuncAttributeMaxDynamicSharedMemorySize, ATTN_SMEM);

    // prep: round hs and o_w, pack+round qkv weights/bias
    {
        int n4 = MTOT * HID / 4;
        round4_kernel<<<(n4 + 255) / 256, 256>>>((const float4*)hs, (float4*)phsr, n4);
        int m4 = HID * HID / 4;
        round4_kernel<<<(m4 + 255) / 256, 256>>>((const float4*)o_w, (float4*)powr, m4);
        int tp = HID * NQKV;
        pack_qkv_kernel<<<(tp + 255) / 256, 256>>>(q_w, k_w, v_w, q_b, k_b, v_b, pwqkv, pbqkv);
    }
    // fused QKV projection: [4096,896] @ [896,1152] + b ; V cols rounded
    gemm_tf32<<<dim3(9, 32), 256, GEMM_SMEM>>>(phsr, pwqkv, pbqkv, pqkv, NQKV, HID, 1024);
    // RoPE on Q and K (K rounded)
    {
        int tot = MTOT * (HQ + HKV) * 32;
        rope_qkv<<<(tot + 255) / 256, 256>>>(pqkv, pos);
    }
    // causal GQA attention
    attn_mma<<<dim3(BB * HQ, NN / 128), 256, ATTN_SMEM>>>(pqkv, po);
    // output projection: [4096,896] @ [896,896] (no rounding of final out)
    gemm_tf32<<<dim3(7, 32), 256, GEMM_SMEM>>>(po, powr, nullptr, out, HID, HQ * DD, 1 << 30);
}

// round 5
// speedup vs baseline: 3.2652x; 1.0547x over previous
#include <cuda_runtime.h>
#include <math.h>

#define BB   2
#define NN   2048
#define HID  896
#define HQ   14
#define HKV  2
#define DD   64
#define MTOT (BB*NN)          // 4096 tokens
#define NQKV 1152             // 896 Q + 128 K + 128 V

// ---- scratch (device globals: no allocations allowed) ----
__device__ float g_qkv[MTOT*NQKV];   // fused QKV proj output, row stride 1152
__device__ float g_o[MTOT*HQ*DD];    // attention out (tf32-rounded)
__device__ float g_hsr[MTOT*HID];    // tf32-rounded hidden_states
__device__ float g_wqkv[HID*NQKV];   // packed+rounded [896][1152] weight
__device__ float g_bqkv[NQKV];       // packed bias
__device__ float g_owr[HID*HID];     // rounded o_w

// ============================================================
// helpers
// ============================================================
__device__ __forceinline__ unsigned f2tf32(float f) {
    unsigned u;
    asm("cvt.rna.tf32.f32 %0, %1;" : "=r"(u) : "f"(f));
    return u;
}
__device__ __forceinline__ float rnd_tf32(float f) {
    return __uint_as_float(f2tf32(f));
}
__device__ __forceinline__ float ex2f(float x) {
    float y;
    asm("ex2.approx.ftz.f32 %0, %1;" : "=f"(y) : "f"(x));
    return y;
}
__device__ __forceinline__ void mma_tf32(float c[4],
    unsigned a0, unsigned a1, unsigned a2, unsigned a3,
    unsigned b0, unsigned b1)
{
    asm volatile(
        "mma.sync.aligned.m16n8k8.row.col.f32.tf32.tf32.f32 "
        "{%0,%1,%2,%3}, {%4,%5,%6,%7}, {%8,%9}, {%0,%1,%2,%3};\n"
        : "+f"(c[0]), "+f"(c[1]), "+f"(c[2]), "+f"(c[3])
        : "r"(a0), "r"(a1), "r"(a2), "r"(a3), "r"(b0), "r"(b1));
}
__device__ __forceinline__ void cp_async16(void* sdst, const void* gsrc) {
    unsigned sa = (unsigned)__cvta_generic_to_shared(sdst);
    asm volatile("cp.async.cg.shared.global [%0], [%1], 16;\n"
                 :: "r"(sa), "l"(gsrc));
}
__device__ __forceinline__ void cp_commit() {
    asm volatile("cp.async.commit_group;\n");
}
__device__ __forceinline__ void cp_wait0() {
    asm volatile("cp.async.wait_group 0;\n");
}

// ============================================================
// prep kernels
// ============================================================
__global__ void round4_kernel(const float4* __restrict__ src,
                              float4* __restrict__ dst, int n4)
{
    int idx = blockIdx.x * blockDim.x + threadIdx.x;
    if (idx >= n4) return;
    float4 v = src[idx];
    v.x = rnd_tf32(v.x); v.y = rnd_tf32(v.y);
    v.z = rnd_tf32(v.z); v.w = rnd_tf32(v.w);
    dst[idx] = v;
}

__global__ void pack_qkv_kernel(
    const float* __restrict__ qw, const float* __restrict__ kw,
    const float* __restrict__ vw, const float* __restrict__ qb,
    const float* __restrict__ kb, const float* __restrict__ vb,
    float* __restrict__ w, float* __restrict__ bias)
{
    int idx = blockIdx.x * blockDim.x + threadIdx.x;
    const int total = HID * NQKV;
    if (idx < total) {
        int row = idx / NQKV, col = idx % NQKV;
        float v = (col < 896) ? qw[row * 896 + col]
                : (col < 1024) ? kw[row * 128 + (col - 896)]
                               : vw[row * 128 + (col - 1024)];
        w[idx] = rnd_tf32(v);
    }
    if (idx < NQKV) {
        bias[idx] = (idx < 896) ? qb[idx]
                  : (idx < 1024) ? kb[idx - 896] : vb[idx - 1024];
    }
}

// ============================================================
// tf32 GEMM core (inputs pre-rounded). 128x128x32 tiles,
// cp.async double-buffered, 8 warps (2x4). 2 CTAs/SM (128 regs).
// ============================================================
__device__ __forceinline__ void gemm_core(
    const float* __restrict__ A, const float* __restrict__ B,
    const float* __restrict__ bias, float* __restrict__ C,
    int N, int K, int bx, int by, bool round_out)
{
    extern __shared__ char dynsm[];
    float (*As)[128][36]  = reinterpret_cast<float(*)[128][36]>(dynsm);
    float (*Bs)[32][136]  = reinterpret_cast<float(*)[32][136]>(dynsm + 2*128*36*4);

    const int tid = threadIdx.x;
    const int lane = tid & 31;
    const int warp = tid >> 5;
    const int warpM = warp >> 2;
    const int warpN = warp & 3;

    const float* Ab = A + (size_t)by * 128 * K;
    const float* Bb = B + (size_t)bx * 128;

    const int a_row = tid >> 1, a_c0 = (tid & 1) * 16;
    const int b_row = tid >> 3, b_c0 = (tid & 7) * 16;
    const int qrow = lane >> 2, qk = lane & 3;

    float acc[4][4][4];
#pragma unroll
    for (int mf = 0; mf < 4; mf++)
#pragma unroll
        for (int nf = 0; nf < 4; nf++)
#pragma unroll
            for (int i = 0; i < 4; i++) acc[mf][nf][i] = 0.f;

    const int NKT = K / 32;

#pragma unroll
    for (int v = 0; v < 4; v++) {
        cp_async16(&As[0][a_row][a_c0 + v * 4], Ab + (size_t)a_row * K + a_c0 + v * 4);
        cp_async16(&Bs[0][b_row][b_c0 + v * 4], Bb + (size_t)b_row * N + b_c0 + v * 4);
    }
    cp_commit();

    for (int kt = 0; kt < NKT; kt++) {
        cp_wait0();
        __syncthreads();
        const int cur = kt & 1;
        if (kt + 1 < NKT) {
            const int kofs = (kt + 1) * 32;
#pragma unroll
            for (int v = 0; v < 4; v++) {
                cp_async16(&As[cur ^ 1][a_row][a_c0 + v * 4],
                           Ab + (size_t)a_row * K + kofs + a_c0 + v * 4);
                cp_async16(&Bs[cur ^ 1][b_row][b_c0 + v * 4],
                           Bb + (size_t)(kofs + b_row) * N + b_c0 + v * 4);
            }
        }
        cp_commit();

#pragma unroll
        for (int ch = 0; ch < 4; ch++) {
            unsigned af[4][4];
#pragma unroll
            for (int mf = 0; mf < 4; mf++) {
                int r = warpM * 64 + mf * 16 + qrow;
                af[mf][0] = __float_as_uint(As[cur][r][ch * 8 + qk]);
                af[mf][1] = __float_as_uint(As[cur][r + 8][ch * 8 + qk]);
                af[mf][2] = __float_as_uint(As[cur][r][ch * 8 + 4 + qk]);
                af[mf][3] = __float_as_uint(As[cur][r + 8][ch * 8 + 4 + qk]);
            }
#pragma unroll
            for (int nf = 0; nf < 4; nf++) {
                int col = warpN * 32 + nf * 8 + qrow;
                unsigned b0 = __float_as_uint(Bs[cur][ch * 8 + qk][col]);
                unsigned b1 = __float_as_uint(Bs[cur][ch * 8 + 4 + qk][col]);
#pragma unroll
                for (int mf = 0; mf < 4; mf++)
                    mma_tf32(acc[mf][nf], af[mf][0], af[mf][1], af[mf][2], af[mf][3], b0, b1);
            }
        }
    }

#pragma unroll
    for (int nf = 0; nf < 4; nf++) {
        int col = bx * 128 + warpN * 32 + nf * 8 + qk * 2;
        float b0 = bias ? bias[col] : 0.f;
        float b1 = bias ? bias[col + 1] : 0.f;
#pragma unroll
        for (int mf = 0; mf < 4; mf++) {
            int row = by * 128 + warpM * 64 + mf * 16 + qrow;
            float2 o0 = { acc[mf][nf][0] + b0, acc[mf][nf][1] + b1 };
            float2 o1 = { acc[mf][nf][2] + b0, acc[mf][nf][3] + b1 };
            if (round_out) {
                o0.x = rnd_tf32(o0.x); o0.y = rnd_tf32(o0.y);
                o1.x = rnd_tf32(o1.x); o1.y = rnd_tf32(o1.y);
            }
            *(float2*)(C + (size_t)row * N + col) = o0;
            *(float2*)(C + (size_t)(row + 8) * N + col) = o1;
        }
    }
}

__global__ __launch_bounds__(256, 2) void gemm_tf32(
    const float* __restrict__ A, const float* __restrict__ B,
    const float* __restrict__ bias, float* __restrict__ C,
    int N, int K, int round_from_col)
{
    gemm_core(A, B, bias, C, N, K, blockIdx.x, blockIdx.y,
              (int)blockIdx.x * 128 >= round_from_col);
}

// ============================================================
// RoPE in place on g_qkv (Q cols 0..895, K cols 896..1023).
// ============================================================
__global__ void rope_qkv(float* __restrict__ qkv, const int* __restrict__ pos)
{
    int idx = blockIdx.x * blockDim.x + threadIdx.x;
    const int tot = MTOT * (HQ + HKV) * 32;
    if (idx >= tot) return;
    int i = idx & 31;
    int slot = (idx >> 5) & 15;
    int t = idx >> 9;
    float p = (float)pos[t];
    const float cexp = -0.622861517791378f;  // -log2(1e6)/32
    float inv = exp2f((float)i * cexp);
    float ang = p * inv;
    float sn, cs;
    sincosf(ang, &sn, &cs);
    int col = (slot < HQ) ? slot * DD : 896 + (slot - HQ) * DD;
    size_t base = (size_t)t * NQKV + col + i;
    float x1 = qkv[base], x2 = qkv[base + 32];
    float r1 = x1 * cs - x2 * sn;
    float r2 = x2 * cs + x1 * sn;
    if (slot >= HQ) { r1 = rnd_tf32(r1); r2 = rnd_tf32(r2); }
    qkv[base]      = r1;
    qkv[base + 32] = r2;
}

// ============================================================
// Causal GQA flash attention, tf32 mma.sync + cp.async pipeline.
// 128 threads = 4 warps, q-tile 64 rows, 3 CTAs/SM.
// grid = (B*HQ, NN/64).
// ============================================================
__global__ __launch_bounds__(128, 3) void attn_mma(
    const float* __restrict__ QKV, float* __restrict__ O)
{
    extern __shared__ char dynsm[];
    float (*ks)[64][68] = reinterpret_cast<float(*)[64][68]>(dynsm);
    float (*vs)[64][72] = reinterpret_cast<float(*)[64][72]>(dynsm + 2*64*68*4);

    const int bh = blockIdx.x;
    const int b = bh / HQ, h = bh % HQ;
    const int q0 = ((int)gridDim.y - 1 - (int)blockIdx.y) * 64;  // heavy first
    const int kh = h / (HQ / HKV);
    const int tid = threadIdx.x, warp = tid >> 5, lane = tid & 31;
    const int qrow = lane >> 2, qk = lane & 3;
    const float QSCALE = 0.125f * 1.44269504f;  // scale * log2(e)

    const float* Kb = QKV + (size_t)(b * NN) * NQKV + 896 + kh * DD;
    const float* Vb = QKV + (size_t)(b * NN) * NQKV + 1024 + kh * DD;

    const int ld_r = tid >> 4, ld_c = (tid & 15) * 4;  // 8 rows/pass, 8 passes

#pragma unroll
    for (int t = 0; t < 8; t++) {
        int r = ld_r + t * 8;
        cp_async16(&ks[0][r][ld_c], Kb + (size_t)r * NQKV + ld_c);
        cp_async16(&vs[0][r][ld_c], Vb + (size_t)r * NQKV + ld_c);
    }
    cp_commit();

    // --- Q fragments in registers ---
    unsigned qa[8][4];
    {
        const int r0 = q0 + warp * 16 + qrow;
        const float* qp0 = QKV + (size_t)(b * NN + r0) * NQKV + h * DD;
        const float* qp1 = qp0 + (size_t)8 * NQKV;
#pragma unroll
        for (int ch = 0; ch < 8; ch++) {
            qa[ch][0] = f2tf32(qp0[ch * 8 + qk] * QSCALE);
            qa[ch][1] = f2tf32(qp1[ch * 8 + qk] * QSCALE);
            qa[ch][2] = f2tf32(qp0[ch * 8 + 4 + qk] * QSCALE);
            qa[ch][3] = f2tf32(qp1[ch * 8 + 4 + qk] * QSCALE);
        }
    }

    float o[8][4];
#pragma unroll
    for (int nf = 0; nf < 8; nf++)
#pragma unroll
        for (int i = 0; i < 4; i++) o[nf][i] = 0.f;
    float m0 = -1e30f, m1 = -1e30f, l0 = 0.f, l1 = 0.f;

    const int r0g = q0 + warp * 16 + qrow;
    const int r1g = r0g + 8;
    const int ktiles = q0 / 64 + 1;
    const int kt_diag = ktiles - 1;
    const int srcA = (lane & ~3) | (qk >> 1);
    const int srcB = srcA | 2;

    for (int kt = 0; kt < ktiles; kt++) {
        cp_wait0();
        __syncthreads();
        const int cur = kt & 1;
        if (kt + 1 < ktiles) {
            const int base = (kt + 1) * 64;
#pragma unroll
            for (int t = 0; t < 8; t++) {
                int r = ld_r + t * 8;
                cp_async16(&ks[cur ^ 1][r][ld_c],
                           Kb + (size_t)(base + r) * NQKV + ld_c);
                cp_async16(&vs[cur ^ 1][r][ld_c],
                           Vb + (size_t)(base + r) * NQKV + ld_c);
            }
        }
        cp_commit();

        // ---- S = Q @ K^T (log2-scaled) ----
        float sc[8][4];
#pragma unroll
        for (int nf = 0; nf < 8; nf++)
#pragma unroll
            for (int i = 0; i < 4; i++) sc[nf][i] = 0.f;
#pragma unroll
        for (int ch = 0; ch < 8; ch++) {
#pragma unroll
            for (int nf = 0; nf < 8; nf++) {
                unsigned b0 = __float_as_uint(ks[cur][nf * 8 + qrow][ch * 8 + qk]);
                unsigned b1 = __float_as_uint(ks[cur][nf * 8 + qrow][ch * 8 + 4 + qk]);
                mma_tf32(sc[nf], qa[ch][0], qa[ch][1], qa[ch][2], qa[ch][3], b0, b1);
            }
        }

        // ---- causal mask ----
        if (kt == kt_diag) {
#pragma unroll
            for (int nf = 0; nf < 8; nf++) {
                int c = kt * 64 + nf * 8 + qk * 2;
                if (c > r0g)     sc[nf][0] = -1e30f;
                if (c + 1 > r0g) sc[nf][1] = -1e30f;
                if (c > r1g)     sc[nf][2] = -1e30f;
                if (c + 1 > r1g) sc[nf][3] = -1e30f;
            }
        }

        // ---- online softmax (log2 domain) ----
        float mx0 = -1e30f, mx1 = -1e30f;
#pragma unroll
        for (int nf = 0; nf < 8; nf++) {
            mx0 = fmaxf(mx0, fmaxf(sc[nf][0], sc[nf][1]));
            mx1 = fmaxf(mx1, fmaxf(sc[nf][2], sc[nf][3]));
        }
        mx0 = fmaxf(mx0, __shfl_xor_sync(0xffffffffu, mx0, 1));
        mx0 = fmaxf(mx0, __shfl_xor_sync(0xffffffffu, mx0, 2));
        mx1 = fmaxf(mx1, __shfl_xor_sync(0xffffffffu, mx1, 1));
        mx1 = fmaxf(mx1, __shfl_xor_sync(0xffffffffu, mx1, 2));
        float mn0 = fmaxf(m0, mx0), mn1 = fmaxf(m1, mx1);
        float al0 = ex2f(m0 - mn0), al1 = ex2f(m1 - mn1);
        float s0 = 0.f, s1 = 0.f;
#pragma unroll
        for (int nf = 0; nf < 8; nf++) {
            sc[nf][0] = ex2f(sc[nf][0] - mn0);
            sc[nf][1] = ex2f(sc[nf][1] - mn0);
            sc[nf][2] = ex2f(sc[nf][2] - mn1);
            sc[nf][3] = ex2f(sc[nf][3] - mn1);
            s0 += sc[nf][0] + sc[nf][1];
            s1 += sc[nf][2] + sc[nf][3];
        }
        s0 += __shfl_xor_sync(0xffffffffu, s0, 1);
        s0 += __shfl_xor_sync(0xffffffffu, s0, 2);
        s1 += __shfl_xor_sync(0xffffffffu, s1, 1);
        s1 += __shfl_xor_sync(0xffffffffu, s1, 2);
        l0 = l0 * al0 + s0;  m0 = mn0;
        l1 = l1 * al1 + s1;  m1 = mn1;
#pragma unroll
        for (int nf = 0; nf < 8; nf++) {
            o[nf][0] *= al0; o[nf][1] *= al0;
            o[nf][2] *= al1; o[nf][3] *= al1;
        }

        // ---- O += P @ V ----
#pragma unroll
        for (int jk = 0; jk < 8; jk++) {
            float c0A = __shfl_sync(0xffffffffu, sc[jk][0], srcA);
            float c1A = __shfl_sync(0xffffffffu, sc[jk][1], srcA);
            float c0B = __shfl_sync(0xffffffffu, sc[jk][0], srcB);
            float c1B = __shfl_sync(0xffffffffu, sc[jk][1], srcB);
            float c2A = __shfl_sync(0xffffffffu, sc[jk][2], srcA);
            float c3A = __shfl_sync(0xffffffffu, sc[jk][3], srcA);
            float c2B = __shfl_sync(0xffffffffu, sc[jk][2], srcB);
            float c3B = __shfl_sync(0xffffffffu, sc[jk][3], srcB);
            bool odd = qk & 1;
            unsigned a0 = f2tf32(odd ? c1A : c0A);
            unsigned a1 = f2tf32(odd ? c3A : c2A);
            unsigned a2 = f2tf32(odd ? c1B : c0B);
            unsigned a3 = f2tf32(odd ? c3B : c2B);
#pragma unroll
            for (int jn = 0; jn < 8; jn++) {
                unsigned b0 = __float_as_uint(vs[cur][jk * 8 + qk][jn * 8 + qrow]);
                unsigned b1 = __float_as_uint(vs[cur][jk * 8 + 4 + qk][jn * 8 + qrow]);
                mma_tf32(o[jn], a0, a1, a2, a3, b0, b1);
            }
        }
    }

    // ---- normalize + store rounded ----
    float inv0 = 1.0f / (l0 + 1e-8f);
    float inv1 = 1.0f / (l1 + 1e-8f);
    float* op0 = O + (size_t)(b * NN + r0g) * (HQ * DD) + h * DD;
    float* op1 = O + (size_t)(b * NN + r1g) * (HQ * DD) + h * DD;
#pragma unroll
    for (int nf = 0; nf < 8; nf++) {
        int d = nf * 8 + qk * 2;
        float2 w0 = { rnd_tf32(o[nf][0] * inv0), rnd_tf32(o[nf][1] * inv0) };
        float2 w1 = { rnd_tf32(o[nf][2] * inv1), rnd_tf32(o[nf][3] * inv1) };
        *(float2*)(op0 + d) = w0;
        *(float2*)(op1 + d) = w1;
    }
}

// ============================================================
extern "C" void kernel_launch(void* const* d_in, const int* in_sizes, int n_in,
                              void* d_out, int out_size)
{
    const float* hs  = (const float*)d_in[0];
    const int*   pos = (const int*)d_in[1];
    const float* q_w = (const float*)d_in[2];
    const float* q_b = (const float*)d_in[3];
    const float* k_w = (const float*)d_in[4];
    const float* k_b = (const float*)d_in[5];
    const float* v_w = (const float*)d_in[6];
    const float* v_b = (const float*)d_in[7];
    const float* o_w = (const float*)d_in[8];
    float* out = (float*)d_out;

    float *pqkv, *po, *phsr, *pwqkv, *pbqkv, *powr;
    cudaGetSymbolAddress((void**)&pqkv,  g_qkv);
    cudaGetSymbolAddress((void**)&po,    g_o);
    cudaGetSymbolAddress((void**)&phsr,  g_hsr);
    cudaGetSymbolAddress((void**)&pwqkv, g_wqkv);
    cudaGetSymbolAddress((void**)&pbqkv, g_bqkv);
    cudaGetSymbolAddress((void**)&powr,  g_owr);

    const int GEMM_SMEM = 2*128*36*4 + 2*32*136*4;   // 71680
    const int ATTN_SMEM = 2*64*68*4  + 2*64*72*4;    // 71680
    cudaFuncSetAttribute(gemm_tf32, cudaFuncAttributeMaxDynamicSharedMemorySize, GEMM_SMEM);
    cudaFuncSetAttribute(attn_mma,  cudaFuncAttributeMaxDynamicSharedMemorySize, ATTN_SMEM);

    // prep: round hs and o_w, pack+round qkv weights/bias
    {
        int n4 = MTOT * HID / 4;
        round4_kernel<<<(n4 + 255) / 256, 256>>>((const float4*)hs, (float4*)phsr, n4);
        int m4 = HID * HID / 4;
        round4_kernel<<<(m4 + 255) / 256, 256>>>((const float4*)o_w, (float4*)powr, m4);
        int tp = HID * NQKV;
        pack_qkv_kernel<<<(tp + 255) / 256, 256>>>(q_w, k_w, v_w, q_b, k_b, v_b, pwqkv, pbqkv);
    }
    // fused QKV projection: [4096,896] @ [896,1152] + b ; V cols rounded
    gemm_tf32<<<dim3(9, 32), 256, GEMM_SMEM>>>(phsr, pwqkv, pbqkv, pqkv, NQKV, HID, 1024);
    // RoPE on Q and K (K rounded)
    {
        int tot = MTOT * (HQ + HKV) * 32;
        rope_qkv<<<(tot + 255) / 256, 256>>>(pqkv, pos);
    }
    // causal GQA attention (64-row q-tiles, 4 warps, 3 CTAs/SM)
    attn_mma<<<dim3(BB * HQ, NN / 64), 128, ATTN_SMEM>>>(pqkv, po);
    // output projection: [4096,896] @ [896,896]
    gemm_tf32<<<dim3(7, 32), 256, GEMM_SMEM>>>(po, powr, nullptr, out, HID, HQ * DD, 1 << 30);
}

// round 7
// speedup vs baseline: 6.9790x; 2.1374x over previous
#include <cuda_runtime.h>
#include <cuda_fp16.h>
#include <math.h>
#include <stdint.h>

#define BB   2
#define NN   2048
#define HID  896
#define HQ   14
#define HKV  2
#define DD   64
#define MTOT (BB*NN)          // 4096 tokens
#define NQKV 1152             // 896 Q + 128 K + 128 V

// ---- scratch (device globals: no allocations allowed) ----
__device__ float  g_qkv[MTOT*NQKV];    // fused QKV proj output (fp32)
__device__ __half g_kvh[MTOT*256];     // roped K (cols 0..127) + V (128..255), fp16
__device__ __half g_oh[MTOT*HID];      // attention out, fp16
__device__ __half g_hsh[MTOT*HID];     // fp16 hidden_states
__device__ __half g_wqkvh[NQKV*HID];   // packed TRANSPOSED [1152][896] fp16
__device__ float  g_bqkv[NQKV];        // packed bias fp32
__device__ __half g_owh[HID*HID];      // TRANSPOSED o_w [out][in] fp16

// ============================================================
// helpers
// ============================================================
__device__ __forceinline__ float ex2f(float x) {
    float y;
    asm("ex2.approx.ftz.f32 %0, %1;" : "=f"(y) : "f"(x));
    return y;
}
__device__ __forceinline__ void mma_f16(float c[4],
    uint32_t a0, uint32_t a1, uint32_t a2, uint32_t a3,
    uint32_t b0, uint32_t b1)
{
    asm volatile(
        "mma.sync.aligned.m16n8k16.row.col.f32.f16.f16.f32 "
        "{%0,%1,%2,%3}, {%4,%5,%6,%7}, {%8,%9}, {%0,%1,%2,%3};\n"
        : "+f"(c[0]), "+f"(c[1]), "+f"(c[2]), "+f"(c[3])
        : "r"(a0), "r"(a1), "r"(a2), "r"(a3), "r"(b0), "r"(b1));
}
__device__ __forceinline__ void ldsm_x4(uint32_t& r0, uint32_t& r1,
                                        uint32_t& r2, uint32_t& r3, uint32_t sa)
{
    asm volatile("ldmatrix.sync.aligned.m8n8.x4.shared.b16 {%0,%1,%2,%3}, [%4];"
                 : "=r"(r0), "=r"(r1), "=r"(r2), "=r"(r3) : "r"(sa));
}
__device__ __forceinline__ void ldsm_x2(uint32_t& r0, uint32_t& r1, uint32_t sa)
{
    asm volatile("ldmatrix.sync.aligned.m8n8.x2.shared.b16 {%0,%1}, [%2];"
                 : "=r"(r0), "=r"(r1) : "r"(sa));
}
__device__ __forceinline__ void ldsm_x2_trans(uint32_t& r0, uint32_t& r1, uint32_t sa)
{
    asm volatile("ldmatrix.sync.aligned.m8n8.x2.trans.shared.b16 {%0,%1}, [%2];"
                 : "=r"(r0), "=r"(r1) : "r"(sa));
}
__device__ __forceinline__ void cp_async16(void* sdst, const void* gsrc) {
    unsigned sa = (unsigned)__cvta_generic_to_shared(sdst);
    asm volatile("cp.async.cg.shared.global [%0], [%1], 16;\n"
                 :: "r"(sa), "l"(gsrc));
}
__device__ __forceinline__ void cp_commit() {
    asm volatile("cp.async.commit_group;\n");
}
__device__ __forceinline__ void cp_wait0() {
    asm volatile("cp.async.wait_group 0;\n");
}
__device__ __forceinline__ uint32_t h2pack(float x, float y) {
    __half2 h = __floats2half2_rn(x, y);
    return *(uint32_t*)&h;
}

// ============================================================
// prep kernels
// ============================================================
__global__ void hs2h_kernel(const float4* __restrict__ src,
                            __half* __restrict__ dst, int n4)
{
    int idx = blockIdx.x * blockDim.x + threadIdx.x;
    if (idx >= n4) return;
    float4 v = src[idx];
    __half2 h0 = __floats2half2_rn(v.x, v.y);
    __half2 h1 = __floats2half2_rn(v.z, v.w);
    *(uint2*)(dst + idx * 4) = make_uint2(*(uint32_t*)&h0, *(uint32_t*)&h1);
}

// o_w [896(in)][896(out)] -> owh[out][in] fp16
__global__ void ow_h_kernel(const float* __restrict__ src, __half* __restrict__ dst)
{
    int idx = blockIdx.x * blockDim.x + threadIdx.x;
    if (idx >= HID * HID) return;
    int n = idx / HID, k = idx % HID;
    dst[idx] = __float2half(src[(size_t)k * HID + n]);
}

// pack q/k/v weights transposed fp16: w[n][k]
__global__ void pack_qkv_h_kernel(
    const float* __restrict__ qw, const float* __restrict__ kw,
    const float* __restrict__ vw, const float* __restrict__ qb,
    const float* __restrict__ kb, const float* __restrict__ vb,
    __half* __restrict__ w, float* __restrict__ bias)
{
    int idx = blockIdx.x * blockDim.x + threadIdx.x;
    const int total = NQKV * HID;
    if (idx < total) {
        int n = idx / HID, k = idx % HID;
        float v = (n < 896) ? qw[(size_t)k * 896 + n]
                : (n < 1024) ? kw[(size_t)k * 128 + (n - 896)]
                             : vw[(size_t)k * 128 + (n - 1024)];
        w[idx] = __float2half(v);
    }
    if (idx < NQKV) {
        bias[idx] = (idx < 896) ? qb[idx]
                  : (idx < 1024) ? kb[idx - 896] : vb[idx - 1024];
    }
}

// ============================================================
// fp16 mma GEMM: C[M,N] = A[M,K] @ Bt[N,K]^T (+bias), fp32 out.
// 128x128 tile, BK=64, 256 threads = 8 warps (2x4), warp 64x32.
// smem: As[2][128][72]h + Bs[2][128][72]h = 73728 B. 2 CTAs/SM.
// ============================================================
__global__ __launch_bounds__(256, 2) void gemm_h(
    const __half* __restrict__ A, const __half* __restrict__ Bt,
    const float* __restrict__ bias, float* __restrict__ C,
    int Nc, int K)
{
    extern __shared__ __align__(128) char dynsm[];
    __half* As = (__half*)dynsm;                  // [2][128*72]
    __half* Bs = As + 2 * 128 * 72;               // [2][128*72]
    const uint32_t As_u = (uint32_t)__cvta_generic_to_shared(As);
    const uint32_t Bs_u = (uint32_t)__cvta_generic_to_shared(Bs);
    const int STG = 128 * 72;                     // halfs per stage

    const int tid = threadIdx.x;
    const int lane = tid & 31;
    const int warp = tid >> 5;
    const int warpM = warp >> 2, warpN = warp & 3;
    const int bx = blockIdx.x, by = blockIdx.y;
    const int qrow = lane >> 2, qk = lane & 3;

    const __half* Ag = A  + (size_t)(by * 128) * K;
    const __half* Bg = Bt + (size_t)(bx * 128) * K;
    const int ld_row = tid >> 3, ld_ch = tid & 7;   // 128 rows x 8 chunks, 4 passes

    float acc[4][4][4];
#pragma unroll
    for (int mf = 0; mf < 4; mf++)
#pragma unroll
        for (int nf = 0; nf < 4; nf++)
#pragma unroll
            for (int i = 0; i < 4; i++) acc[mf][nf][i] = 0.f;

    // ldmatrix lane addressing (halfs -> bytes, row stride 144B)
    const int a_row_l = warpM * 64 + (lane & 7) + ((lane >> 3) & 1) * 8;
    const int a_ksel  = (lane >> 4) & 1;
    const int b_row_l = warpN * 32 + (lane & 7);
    const int b_ksel  = (lane >> 3) & 1;

    // prologue: stage 0
#pragma unroll
    for (int t = 0; t < 4; t++) {
        int row = ld_row + t * 32;
        cp_async16(As + row * 72 + ld_ch * 8, Ag + (size_t)row * K + ld_ch * 8);
        cp_async16(Bs + row * 72 + ld_ch * 8, Bg + (size_t)row * K + ld_ch * 8);
    }
    cp_commit();

    const int NKT = K / 64;
    for (int kt = 0; kt < NKT; kt++) {
        cp_wait0();
        __syncthreads();
        const int cur = kt & 1;
        if (kt + 1 < NKT) {
            const int ko = (kt + 1) * 64;
            __half* Ad = As + (cur ^ 1) * STG;
            __half* Bd = Bs + (cur ^ 1) * STG;
#pragma unroll
            for (int t = 0; t < 4; t++) {
                int row = ld_row + t * 32;
                cp_async16(Ad + row * 72 + ld_ch * 8, Ag + (size_t)row * K + ko + ld_ch * 8);
                cp_async16(Bd + row * 72 + ld_ch * 8, Bg + (size_t)row * K + ko + ld_ch * 8);
            }
        }
        cp_commit();

        const uint32_t Ab = As_u + cur * STG * 2;
        const uint32_t Bb = Bs_u + cur * STG * 2;
#pragma unroll
        for (int ch = 0; ch < 4; ch++) {
            uint32_t af[4][4];
#pragma unroll
            for (int mf = 0; mf < 4; mf++) {
                uint32_t sa = Ab + (a_row_l + mf * 16) * 144 + ch * 32 + a_ksel * 16;
                ldsm_x4(af[mf][0], af[mf][1], af[mf][2], af[mf][3], sa);
            }
#pragma unroll
            for (int nf = 0; nf < 4; nf++) {
                uint32_t b0, b1;
                uint32_t sb = Bb + (b_row_l + nf * 8) * 144 + ch * 32 + b_ksel * 16;
                ldsm_x2(b0, b1, sb);
#pragma unroll
                for (int mf = 0; mf < 4; mf++)
                    mma_f16(acc[mf][nf], af[mf][0], af[mf][1], af[mf][2], af[mf][3], b0, b1);
            }
        }
    }

    // epilogue: fp32 out (+bias)
#pragma unroll
    for (int nf = 0; nf < 4; nf++) {
        int col = bx * 128 + warpN * 32 + nf * 8 + qk * 2;
        float b0 = bias ? bias[col] : 0.f;
        float b1 = bias ? bias[col + 1] : 0.f;
#pragma unroll
        for (int mf = 0; mf < 4; mf++) {
            int row = by * 128 + warpM * 64 + mf * 16 + qrow;
            float2 o0 = { acc[mf][nf][0] + b0, acc[mf][nf][1] + b1 };
            float2 o1 = { acc[mf][nf][2] + b0, acc[mf][nf][3] + b1 };
            *(float2*)(C + (size_t)row * Nc + col) = o0;
            *(float2*)(C + (size_t)(row + 8) * Nc + col) = o1;
        }
    }
}

// ============================================================
// RoPE: Q in place (fp32), K roped -> g_kvh fp16, V copied -> g_kvh fp16.
// slots: 0..13 Q, 14..15 K, 16..17 V
// ============================================================
__global__ void rope_qkv(float* __restrict__ qkv, __half* __restrict__ kvh,
                         const int* __restrict__ pos)
{
    int idx = blockIdx.x * blockDim.x + threadIdx.x;
    const int tot = MTOT * 18 * 32;
    if (idx >= tot) return;
    int i = idx & 31;
    int slot = (idx >> 5) % 18;
    int t = idx / (32 * 18);

    if (slot >= 16) {              // V: convert only
        int h = slot - 16;
        size_t src = (size_t)t * NQKV + 1024 + h * DD + i;
        size_t dst = (size_t)t * 256 + 128 + h * DD + i;
        kvh[dst]      = __float2half(qkv[src]);
        kvh[dst + 32] = __float2half(qkv[src + 32]);
        return;
    }
    float p = (float)pos[t];
    const float cexp = -0.622861517791378f;  // -log2(1e6)/32
    float inv = exp2f((float)i * cexp);
    float ang = p * inv;
    float sn, cs;
    sincosf(ang, &sn, &cs);
    if (slot < HQ) {               // Q: rotate fp32 in place
        size_t base = (size_t)t * NQKV + slot * DD + i;
        float x1 = qkv[base], x2 = qkv[base + 32];
        qkv[base]      = x1 * cs - x2 * sn;
        qkv[base + 32] = x2 * cs + x1 * sn;
    } else {                       // K: rotate -> fp16
        int h = slot - HQ;
        size_t src = (size_t)t * NQKV + 896 + h * DD + i;
        float x1 = qkv[src], x2 = qkv[src + 32];
        size_t dst = (size_t)t * 256 + h * DD + i;
        kvh[dst]      = __float2half(x1 * cs - x2 * sn);
        kvh[dst + 32] = __float2half(x2 * cs + x1 * sn);
    }
}

// ============================================================
// Causal GQA flash attention, fp16 mma.sync.
// 128 threads = 4 warps, q-tile 64 rows. K/V fp16 from g_kvh.
// smem: ks[2][64][72]h + vs[2][64][72]h = 36864 B.
// P->A-frag conversion is shuffle-free (layout identity).
// ============================================================
__global__ __launch_bounds__(128, 4) void attn_mma(
    const float* __restrict__ QKV, const __half* __restrict__ KVH,
    __half* __restrict__ O)
{
    extern __shared__ __align__(128) char dynsm2[];
    __half* ks = (__half*)dynsm2;             // [2][64*72]
    __half* vs = ks + 2 * 64 * 72;            // [2][64*72]
    const uint32_t vs_u = (uint32_t)__cvta_generic_to_shared(vs);
    const int STG = 64 * 72;

    const int bh = blockIdx.x;
    const int b = bh / HQ, h = bh % HQ;
    const int q0 = ((int)gridDim.y - 1 - (int)blockIdx.y) * 64;  // heavy first
    const int kh = h / (HQ / HKV);
    const int tid = threadIdx.x, warp = tid >> 5, lane = tid & 31;
    const int qrow = lane >> 2, qk = lane & 3;
    const float QSCALE = 0.125f * 1.44269504f;  // scale * log2(e)

    const __half* Kb = KVH + (size_t)(b * NN) * 256 + kh * DD;
    const __half* Vb = KVH + (size_t)(b * NN) * 256 + 128 + kh * DD;

    const int ld_row = tid >> 3, ld_ch = tid & 7;  // 16 rows/pass, 4 passes

    // prologue: tile 0 -> stage 0
#pragma unroll
    for (int t = 0; t < 4; t++) {
        int r = ld_row + t * 16;
        cp_async16(ks + r * 72 + ld_ch * 8, Kb + (size_t)r * 256 + ld_ch * 8);
        cp_async16(vs + r * 72 + ld_ch * 8, Vb + (size_t)r * 256 + ld_ch * 8);
    }
    cp_commit();

    // --- Q fragments (fp32 -> fp16, scaled) ---
    uint32_t qa[4][4];
    {
        const int r0 = q0 + warp * 16 + qrow;
        const float* qp0 = QKV + (size_t)(b * NN + r0) * NQKV + h * DD;
        const float* qp1 = qp0 + (size_t)8 * NQKV;
#pragma unroll
        for (int ch = 0; ch < 4; ch++) {
            float2 v0 = *(const float2*)(qp0 + ch * 16 + 2 * qk);
            float2 v1 = *(const float2*)(qp1 + ch * 16 + 2 * qk);
            float2 v2 = *(const float2*)(qp0 + ch * 16 + 8 + 2 * qk);
            float2 v3 = *(const float2*)(qp1 + ch * 16 + 8 + 2 * qk);
            qa[ch][0] = h2pack(v0.x * QSCALE, v0.y * QSCALE);
            qa[ch][1] = h2pack(v1.x * QSCALE, v1.y * QSCALE);
            qa[ch][2] = h2pack(v2.x * QSCALE, v2.y * QSCALE);
            qa[ch][3] = h2pack(v3.x * QSCALE, v3.y * QSCALE);
        }
    }

    float o[8][4];
#pragma unroll
    for (int nf = 0; nf < 8; nf++)
#pragma unroll
        for (int i = 0; i < 4; i++) o[nf][i] = 0.f;
    float m0 = -1e30f, m1 = -1e30f, l0 = 0.f, l1 = 0.f;

    const int r0g = q0 + warp * 16 + qrow;
    const int r1g = r0g + 8;
    const int ktiles = q0 / 64 + 1;
    const int kt_diag = ktiles - 1;

    for (int kt = 0; kt < ktiles; kt++) {
        cp_wait0();
        __syncthreads();
        const int cur = kt & 1;
        if (kt + 1 < ktiles) {
            const int base = (kt + 1) * 64;
            __half* kd = ks + (cur ^ 1) * STG;
            __half* vd = vs + (cur ^ 1) * STG;
#pragma unroll
            for (int t = 0; t < 4; t++) {
                int r = ld_row + t * 16;
                cp_async16(kd + r * 72 + ld_ch * 8, Kb + (size_t)(base + r) * 256 + ld_ch * 8);
                cp_async16(vd + r * 72 + ld_ch * 8, Vb + (size_t)(base + r) * 256 + ld_ch * 8);
            }
        }
        cp_commit();

        const __half* kc = ks + cur * STG;

        // ---- S = Q @ K^T (log2-scaled), fp16 mma ----
        float sc[8][4];
#pragma unroll
        for (int nf = 0; nf < 8; nf++)
#pragma unroll
            for (int i = 0; i < 4; i++) sc[nf][i] = 0.f;
#pragma unroll
        for (int ch = 0; ch < 4; ch++) {
#pragma unroll
            for (int nf = 0; nf < 8; nf++) {
                const __half* kp = kc + (nf * 8 + qrow) * 72 + ch * 16 + 2 * qk;
                uint32_t b0 = *(const uint32_t*)kp;
                uint32_t b1 = *(const uint32_t*)(kp + 8);
                mma_f16(sc[nf], qa[ch][0], qa[ch][1], qa[ch][2], qa[ch][3], b0, b1);
            }
        }

        // ---- causal mask ----
        if (kt == kt_diag) {
#pragma unroll
            for (int nf = 0; nf < 8; nf++) {
                int c = kt * 64 + nf * 8 + qk * 2;
                if (c > r0g)     sc[nf][0] = -1e30f;
                if (c + 1 > r0g) sc[nf][1] = -1e30f;
                if (c > r1g)     sc[nf][2] = -1e30f;
                if (c + 1 > r1g) sc[nf][3] = -1e30f;
            }
        }

        // ---- online softmax (log2 domain) ----
        float mx0 = -1e30f, mx1 = -1e30f;
#pragma unroll
        for (int nf = 0; nf < 8; nf++) {
            mx0 = fmaxf(mx0, fmaxf(sc[nf][0], sc[nf][1]));
            mx1 = fmaxf(mx1, fmaxf(sc[nf][2], sc[nf][3]));
        }
        mx0 = fmaxf(mx0, __shfl_xor_sync(0xffffffffu, mx0, 1));
        mx0 = fmaxf(mx0, __shfl_xor_sync(0xffffffffu, mx0, 2));
        mx1 = fmaxf(mx1, __shfl_xor_sync(0xffffffffu, mx1, 1));
        mx1 = fmaxf(mx1, __shfl_xor_sync(0xffffffffu, mx1, 2));
        float mn0 = fmaxf(m0, mx0), mn1 = fmaxf(m1, mx1);
        float al0 = ex2f(m0 - mn0), al1 = ex2f(m1 - mn1);
        float s0 = 0.f, s1 = 0.f;
#pragma unroll
        for (int nf = 0; nf < 8; nf++) {
            sc[nf][0] = ex2f(sc[nf][0] - mn0);
            sc[nf][1] = ex2f(sc[nf][1] - mn0);
            sc[nf][2] = ex2f(sc[nf][2] - mn1);
            sc[nf][3] = ex2f(sc[nf][3] - mn1);
            s0 += sc[nf][0] + sc[nf][1];
            s1 += sc[nf][2] + sc[nf][3];
        }
        s0 += __shfl_xor_sync(0xffffffffu, s0, 1);
        s0 += __shfl_xor_sync(0xffffffffu, s0, 2);
        s1 += __shfl_xor_sync(0xffffffffu, s1, 1);
        s1 += __shfl_xor_sync(0xffffffffu, s1, 2);
        l0 = l0 * al0 + s0;  m0 = mn0;
        l1 = l1 * al1 + s1;  m1 = mn1;
#pragma unroll
        for (int nf = 0; nf < 8; nf++) {
            o[nf][0] *= al0; o[nf][1] *= al0;
            o[nf][2] *= al1; o[nf][3] *= al1;
        }

        // ---- O += P @ V : P A-frag = own C-frag values (no shuffles) ----
        const uint32_t vc_u = vs_u + cur * STG * 2;
#pragma unroll
        for (int jk = 0; jk < 4; jk++) {
            uint32_t a0 = h2pack(sc[2*jk][0],   sc[2*jk][1]);
            uint32_t a1 = h2pack(sc[2*jk][2],   sc[2*jk][3]);
            uint32_t a2 = h2pack(sc[2*jk+1][0], sc[2*jk+1][1]);
            uint32_t a3 = h2pack(sc[2*jk+1][2], sc[2*jk+1][3]);
            uint32_t vaddr_row = jk * 16 + (lane & 15);
#pragma unroll
            for (int jn = 0; jn < 8; jn++) {
                uint32_t b0, b1;
                ldsm_x2_trans(b0, b1, vc_u + vaddr_row * 144 + jn * 16);
                mma_f16(o[jn], a0, a1, a2, a3, b0, b1);
            }
        }
    }

    // ---- normalize + store fp16 (feeds O-proj) ----
    float inv0 = 1.0f / (l0 + 1e-8f);
    float inv1 = 1.0f / (l1 + 1e-8f);
    __half* op0 = O + (size_t)(b * NN + r0g) * HID + h * DD;
    __half* op1 = O + (size_t)(b * NN + r1g) * HID + h * DD;
#pragma unroll
    for (int nf = 0; nf < 8; nf++) {
        int d = nf * 8 + qk * 2;
        *(uint32_t*)(op0 + d) = h2pack(o[nf][0] * inv0, o[nf][1] * inv0);
        *(uint32_t*)(op1 + d) = h2pack(o[nf][2] * inv1, o[nf][3] * inv1);
    }
}

// ============================================================
extern "C" void kernel_launch(void* const* d_in, const int* in_sizes, int n_in,
                              void* d_out, int out_size)
{
    const float* hs  = (const float*)d_in[0];
    const int*   pos = (const int*)d_in[1];
    const float* q_w = (const float*)d_in[2];
    const float* q_b = (const float*)d_in[3];
    const float* k_w = (const float*)d_in[4];
    const float* k_b = (const float*)d_in[5];
    const float* v_w = (const float*)d_in[6];
    const float* v_b = (const float*)d_in[7];
    const float* o_w = (const float*)d_in[8];
    float* out = (float*)d_out;

    float *pqkv, *pbqkv;
    __half *pkvh, *poh, *phsh, *pwqkvh, *powh;
    cudaGetSymbolAddress((void**)&pqkv,   g_qkv);
    cudaGetSymbolAddress((void**)&pkvh,   g_kvh);
    cudaGetSymbolAddress((void**)&poh,    g_oh);
    cudaGetSymbolAddress((void**)&phsh,   g_hsh);
    cudaGetSymbolAddress((void**)&pwqkvh, g_wqkvh);
    cudaGetSymbolAddress((void**)&pbqkv,  g_bqkv);
    cudaGetSymbolAddress((void**)&powh,   g_owh);

    const int GEMM_SMEM = 2 * (128*72 + 128*72) * 2;   // 73728 B
    const int ATTN_SMEM = 2 * (64*72 + 64*72) * 2;     // 36864 B
    cudaFuncSetAttribute(gemm_h,   cudaFuncAttributeMaxDynamicSharedMemorySize, GEMM_SMEM);
    cudaFuncSetAttribute(attn_mma, cudaFuncAttributeMaxDynamicSharedMemorySize, ATTN_SMEM);

    // prep: fp16 conversions + packing
    {
        int n4 = MTOT * HID / 4;
        hs2h_kernel<<<(n4 + 255) / 256, 256>>>((const float4*)hs, phsh, n4);
        int m = HID * HID;
        ow_h_kernel<<<(m + 255) / 256, 256>>>(o_w, powh);
        int tp = NQKV * HID;
        pack_qkv_h_kernel<<<(tp + 255) / 256, 256>>>(q_w, k_w, v_w, q_b, k_b, v_b,
                                                     pwqkvh, pbqkv);
    }
    // fused QKV projection: [4096,896]h @ [896,1152]h + b -> fp32
    gemm_h<<<dim3(9, 32), 256, GEMM_SMEM>>>(phsh, pwqkvh, pbqkv, pqkv, NQKV, HID);
    // RoPE: Q fp32 in place; K roped->fp16; V converted->fp16
    {
        int tot = MTOT * 18 * 32;
        rope_qkv<<<(tot + 255) / 256, 256>>>(pqkv, pkvh, pos);
    }
    // causal GQA attention -> fp16 O
    attn_mma<<<dim3(BB * HQ, NN / 64), 128, ATTN_SMEM>>>(pqkv, pkvh, poh);
    // output projection: [4096,896]h @ [896,896]h -> fp32 out
    gemm_h<<<dim3(7, 32), 256, GEMM_SMEM>>>(poh, powh, nullptr, out, HID, HID);
}

// round 8
// speedup vs baseline: 7.2791x; 1.0430x over previous
#include <cuda_runtime.h>
#include <cuda_fp16.h>
#include <math.h>
#include <stdint.h>

#define BB   2
#define NN   2048
#define HID  896
#define HQ   14
#define HKV  2
#define DD   64
#define MTOT (BB*NN)          // 4096 tokens
#define NQKV 1152             // 896 Q + 128 K + 128 V

// ---- scratch (device globals: no allocations allowed) ----
__device__ float  g_qkv[MTOT*NQKV];    // fused QKV proj output (fp32)
__device__ __half g_kvh[MTOT*256];     // roped K (0..127) + V (128..255), fp16
__device__ __half g_oh[MTOT*HID];      // attention out, fp16
__device__ __half g_hsh[MTOT*HID];     // fp16 hidden_states
__device__ __half g_wqkvh[HID*NQKV];   // packed [896(k)][1152(n)] fp16 (natural)
__device__ float  g_bqkv[NQKV];        // packed bias fp32
__device__ __half g_owh[HID*HID];      // o_w [896(k)][896(n)] fp16 (natural)

// ============================================================
// helpers
// ============================================================
__device__ __forceinline__ float ex2f(float x) {
    float y;
    asm("ex2.approx.ftz.f32 %0, %1;" : "=f"(y) : "f"(x));
    return y;
}
__device__ __forceinline__ void mma_f16(float c[4],
    uint32_t a0, uint32_t a1, uint32_t a2, uint32_t a3,
    uint32_t b0, uint32_t b1)
{
    asm volatile(
        "mma.sync.aligned.m16n8k16.row.col.f32.f16.f16.f32 "
        "{%0,%1,%2,%3}, {%4,%5,%6,%7}, {%8,%9}, {%0,%1,%2,%3};\n"
        : "+f"(c[0]), "+f"(c[1]), "+f"(c[2]), "+f"(c[3])
        : "r"(a0), "r"(a1), "r"(a2), "r"(a3), "r"(b0), "r"(b1));
}
__device__ __forceinline__ void ldsm_x4(uint32_t& r0, uint32_t& r1,
                                        uint32_t& r2, uint32_t& r3, uint32_t sa)
{
    asm volatile("ldmatrix.sync.aligned.m8n8.x4.shared.b16 {%0,%1,%2,%3}, [%4];"
                 : "=r"(r0), "=r"(r1), "=r"(r2), "=r"(r3) : "r"(sa));
}
__device__ __forceinline__ void ldsm_x2_trans(uint32_t& r0, uint32_t& r1, uint32_t sa)
{
    asm volatile("ldmatrix.sync.aligned.m8n8.x2.trans.shared.b16 {%0,%1}, [%2];"
                 : "=r"(r0), "=r"(r1) : "r"(sa));
}
__device__ __forceinline__ void cp_async16(void* sdst, const void* gsrc) {
    unsigned sa = (unsigned)__cvta_generic_to_shared(sdst);
    asm volatile("cp.async.cg.shared.global [%0], [%1], 16;\n"
                 :: "r"(sa), "l"(gsrc));
}
__device__ __forceinline__ void cp_commit() {
    asm volatile("cp.async.commit_group;\n");
}
__device__ __forceinline__ void cp_wait0() {
    asm volatile("cp.async.wait_group 0;\n");
}
__device__ __forceinline__ uint32_t h2pack(float x, float y) {
    __half2 h = __floats2half2_rn(x, y);
    return *(uint32_t*)&h;
}

// ============================================================
// prep kernels (all fully coalesced)
// ============================================================
__global__ void f2h4_kernel(const float4* __restrict__ src,
                            __half* __restrict__ dst, int n4)
{
    int idx = blockIdx.x * blockDim.x + threadIdx.x;
    if (idx >= n4) return;
    float4 v = src[idx];
    __half2 h0 = __floats2half2_rn(v.x, v.y);
    __half2 h1 = __floats2half2_rn(v.z, v.w);
    *(uint2*)(dst + idx * 4) = make_uint2(*(uint32_t*)&h0, *(uint32_t*)&h1);
}

// pack q/k/v weights in natural [k][n] layout, fp16 (coalesced both sides)
__global__ void pack_qkv_kernel(
    const float* __restrict__ qw, const float* __restrict__ kw,
    const float* __restrict__ vw, const float* __restrict__ qb,
    const float* __restrict__ kb, const float* __restrict__ vb,
    __half* __restrict__ w, float* __restrict__ bias)
{
    int idx = blockIdx.x * blockDim.x + threadIdx.x;
    const int total = HID * NQKV;
    if (idx < total) {
        int k = idx / NQKV, n = idx % NQKV;
        float v = (n < 896) ? qw[(size_t)k * 896 + n]
                : (n < 1024) ? kw[(size_t)k * 128 + (n - 896)]
                             : vw[(size_t)k * 128 + (n - 1024)];
        w[idx] = __float2half(v);
    }
    if (idx < NQKV) {
        bias[idx] = (idx < 896) ? qb[idx]
                  : (idx < 1024) ? kb[idx - 896] : vb[idx - 1024];
    }
}

// ============================================================
// fp16 mma GEMM: C[M,N] = A[M,K] @ B[K,N] (+bias), fp32 out.
// A natural [M][K], B natural [K][N] (fragments via ldsm.trans).
// 128x128 tile, BK=64, 256 threads = 8 warps (2x4), warp 64x32.
// smem: As[2][128][72]h + Bs[2][64][136]h = 71680 B. 2 CTAs/SM.
// ============================================================
__global__ __launch_bounds__(256, 2) void gemm_h(
    const __half* __restrict__ A, const __half* __restrict__ B,
    const float* __restrict__ bias, float* __restrict__ C,
    int Nw, int Nc, int K)
{
    extern __shared__ __align__(128) char dynsm[];
    __half* As = (__half*)dynsm;                  // [2][128*72]
    __half* Bs = As + 2 * 128 * 72;               // [2][64*136]
    const uint32_t As_u = (uint32_t)__cvta_generic_to_shared(As);
    const uint32_t Bs_u = (uint32_t)__cvta_generic_to_shared(Bs);
    const int STGA = 128 * 72;
    const int STGB = 64 * 136;

    const int tid = threadIdx.x;
    const int lane = tid & 31;
    const int warp = tid >> 5;
    const int warpM = warp >> 2, warpN = warp & 3;
    const int bx = blockIdx.x, by = blockIdx.y;
    const int qrow = lane >> 2, qk = lane & 3;

    const __half* Ag = A + (size_t)(by * 128) * K;
    const __half* Bg = B + bx * 128;
    const int a_row = tid >> 3, a_ch = tid & 7;   // A: 128 rows x 8 chunks, 4 passes
    const int b_row = tid >> 4, b_ch = tid & 15;  // B: 64 rows x 16 chunks, 4 passes

    float acc[4][4][4];
#pragma unroll
    for (int mf = 0; mf < 4; mf++)
#pragma unroll
        for (int nf = 0; nf < 4; nf++)
#pragma unroll
            for (int i = 0; i < 4; i++) acc[mf][nf][i] = 0.f;

    // ldmatrix lane addressing
    const int a_row_l = warpM * 64 + (lane & 7) + ((lane >> 3) & 1) * 8;
    const int a_ksel  = (lane >> 4) & 1;
    const int b_col_l = warpN * 32;               // + nf*8 halves
    const int b_lane_r = lane & 15;               // k row within 16

    // prologue: stage 0
#pragma unroll
    for (int t = 0; t < 4; t++) {
        int ra = a_row + t * 32;
        cp_async16(As + ra * 72 + a_ch * 8, Ag + (size_t)ra * K + a_ch * 8);
        int rb = b_row + t * 16;
        cp_async16(Bs + rb * 136 + b_ch * 8, Bg + (size_t)rb * Nw + b_ch * 8);
    }
    cp_commit();

    const int NKT = K / 64;
    for (int kt = 0; kt < NKT; kt++) {
        cp_wait0();
        __syncthreads();
        const int cur = kt & 1;
        if (kt + 1 < NKT) {
            const int ko = (kt + 1) * 64;
            __half* Ad = As + (cur ^ 1) * STGA;
            __half* Bd = Bs + (cur ^ 1) * STGB;
#pragma unroll
            for (int t = 0; t < 4; t++) {
                int ra = a_row + t * 32;
                cp_async16(Ad + ra * 72 + a_ch * 8, Ag + (size_t)ra * K + ko + a_ch * 8);
                int rb = b_row + t * 16;
                cp_async16(Bd + rb * 136 + b_ch * 8, Bg + (size_t)(ko + rb) * Nw + b_ch * 8);
            }
        }
        cp_commit();

        const uint32_t Ab = As_u + cur * STGA * 2;
        const uint32_t Bb = Bs_u + cur * STGB * 2;
#pragma unroll
        for (int ch = 0; ch < 4; ch++) {
            uint32_t af[4][4];
#pragma unroll
            for (int mf = 0; mf < 4; mf++) {
                uint32_t sa = Ab + (a_row_l + mf * 16) * 144 + ch * 32 + a_ksel * 16;
                ldsm_x4(af[mf][0], af[mf][1], af[mf][2], af[mf][3], sa);
            }
#pragma unroll
            for (int nf = 0; nf < 4; nf++) {
                uint32_t b0, b1;
                uint32_t sb = Bb + (ch * 16 + b_lane_r) * 272 + (b_col_l + nf * 8) * 2;
                ldsm_x2_trans(b0, b1, sb);
#pragma unroll
                for (int mf = 0; mf < 4; mf++)
                    mma_f16(acc[mf][nf], af[mf][0], af[mf][1], af[mf][2], af[mf][3], b0, b1);
            }
        }
    }

    // epilogue: fp32 out (+bias)
#pragma unroll
    for (int nf = 0; nf < 4; nf++) {
        int col = bx * 128 + warpN * 32 + nf * 8 + qk * 2;
        float b0 = bias ? bias[col] : 0.f;
        float b1 = bias ? bias[col + 1] : 0.f;
#pragma unroll
        for (int mf = 0; mf < 4; mf++) {
            int row = by * 128 + warpM * 64 + mf * 16 + qrow;
            float2 o0 = { acc[mf][nf][0] + b0, acc[mf][nf][1] + b1 };
            float2 o1 = { acc[mf][nf][2] + b0, acc[mf][nf][3] + b1 };
            *(float2*)(C + (size_t)row * Nc + col) = o0;
            *(float2*)(C + (size_t)(row + 8) * Nc + col) = o1;
        }
    }
}

// ============================================================
// RoPE: Q in place (fp32), K roped -> g_kvh fp16, V -> g_kvh fp16.
// slots: 0..13 Q, 14..15 K, 16..17 V
// ============================================================
__global__ void rope_qkv(float* __restrict__ qkv, __half* __restrict__ kvh,
                         const int* __restrict__ pos)
{
    int idx = blockIdx.x * blockDim.x + threadIdx.x;
    const int tot = MTOT * 18 * 32;
    if (idx >= tot) return;
    int i = idx & 31;
    int slot = (idx >> 5) % 18;
    int t = idx / (32 * 18);

    if (slot >= 16) {              // V: convert only
        int h = slot - 16;
        size_t src = (size_t)t * NQKV + 1024 + h * DD + i;
        size_t dst = (size_t)t * 256 + 128 + h * DD + i;
        kvh[dst]      = __float2half(qkv[src]);
        kvh[dst + 32] = __float2half(qkv[src + 32]);
        return;
    }
    float p = (float)pos[t];
    const float cexp = -0.622861517791378f;  // -log2(1e6)/32
    float inv = exp2f((float)i * cexp);
    float ang = p * inv;
    float sn, cs;
    sincosf(ang, &sn, &cs);
    if (slot < HQ) {               // Q: rotate fp32 in place
        size_t base = (size_t)t * NQKV + slot * DD + i;
        float x1 = qkv[base], x2 = qkv[base + 32];
        qkv[base]      = x1 * cs - x2 * sn;
        qkv[base + 32] = x2 * cs + x1 * sn;
    } else {                       // K: rotate -> fp16
        int h = slot - HQ;
        size_t src = (size_t)t * NQKV + 896 + h * DD + i;
        float x1 = qkv[src], x2 = qkv[src + 32];
        size_t dst = (size_t)t * 256 + h * DD + i;
        kvh[dst]      = __float2half(x1 * cs - x2 * sn);
        kvh[dst + 32] = __float2half(x2 * cs + x1 * sn);
    }
}

// ============================================================
// Causal GQA flash attention, fp16 mma.sync. (unchanged from R7)
// ============================================================
__global__ __launch_bounds__(128, 4) void attn_mma(
    const float* __restrict__ QKV, const __half* __restrict__ KVH,
    __half* __restrict__ O)
{
    extern __shared__ __align__(128) char dynsm2[];
    __half* ks = (__half*)dynsm2;             // [2][64*72]
    __half* vs = ks + 2 * 64 * 72;            // [2][64*72]
    const uint32_t vs_u = (uint32_t)__cvta_generic_to_shared(vs);
    const int STG = 64 * 72;

    const int bh = blockIdx.x;
    const int b = bh / HQ, h = bh % HQ;
    const int q0 = ((int)gridDim.y - 1 - (int)blockIdx.y) * 64;  // heavy first
    const int kh = h / (HQ / HKV);
    const int tid = threadIdx.x, warp = tid >> 5, lane = tid & 31;
    const int qrow = lane >> 2, qk = lane & 3;
    const float QSCALE = 0.125f * 1.44269504f;  // scale * log2(e)

    const __half* Kb = KVH + (size_t)(b * NN) * 256 + kh * DD;
    const __half* Vb = KVH + (size_t)(b * NN) * 256 + 128 + kh * DD;

    const int ld_row = tid >> 3, ld_ch = tid & 7;  // 16 rows/pass, 4 passes

#pragma unroll
    for (int t = 0; t < 4; t++) {
        int r = ld_row + t * 16;
        cp_async16(ks + r * 72 + ld_ch * 8, Kb + (size_t)r * 256 + ld_ch * 8);
        cp_async16(vs + r * 72 + ld_ch * 8, Vb + (size_t)r * 256 + ld_ch * 8);
    }
    cp_commit();

    uint32_t qa[4][4];
    {
        const int r0 = q0 + warp * 16 + qrow;
        const float* qp0 = QKV + (size_t)(b * NN + r0) * NQKV + h * DD;
        const float* qp1 = qp0 + (size_t)8 * NQKV;
#pragma unroll
        for (int ch = 0; ch < 4; ch++) {
            float2 v0 = *(const float2*)(qp0 + ch * 16 + 2 * qk);
            float2 v1 = *(const float2*)(qp1 + ch * 16 + 2 * qk);
            float2 v2 = *(const float2*)(qp0 + ch * 16 + 8 + 2 * qk);
            float2 v3 = *(const float2*)(qp1 + ch * 16 + 8 + 2 * qk);
            qa[ch][0] = h2pack(v0.x * QSCALE, v0.y * QSCALE);
            qa[ch][1] = h2pack(v1.x * QSCALE, v1.y * QSCALE);
            qa[ch][2] = h2pack(v2.x * QSCALE, v2.y * QSCALE);
            qa[ch][3] = h2pack(v3.x * QSCALE, v3.y * QSCALE);
        }
    }

    float o[8][4];
#pragma unroll
    for (int nf = 0; nf < 8; nf++)
#pragma unroll
        for (int i = 0; i < 4; i++) o[nf][i] = 0.f;
    float m0 = -1e30f, m1 = -1e30f, l0 = 0.f, l1 = 0.f;

    const int r0g = q0 + warp * 16 + qrow;
    const int r1g = r0g + 8;
    const int ktiles = q0 / 64 + 1;
    const int kt_diag = ktiles - 1;

    for (int kt = 0; kt < ktiles; kt++) {
        cp_wait0();
        __syncthreads();
        const int cur = kt & 1;
        if (kt + 1 < ktiles) {
            const int base = (kt + 1) * 64;
            __half* kd = ks + (cur ^ 1) * STG;
            __half* vd = vs + (cur ^ 1) * STG;
#pragma unroll
            for (int t = 0; t < 4; t++) {
                int r = ld_row + t * 16;
                cp_async16(kd + r * 72 + ld_ch * 8, Kb + (size_t)(base + r) * 256 + ld_ch * 8);
                cp_async16(vd + r * 72 + ld_ch * 8, Vb + (size_t)(base + r) * 256 + ld_ch * 8);
            }
        }
        cp_commit();

        const __half* kc = ks + cur * STG;

        float sc[8][4];
#pragma unroll
        for (int nf = 0; nf < 8; nf++)
#pragma unroll
            for (int i = 0; i < 4; i++) sc[nf][i] = 0.f;
#pragma unroll
        for (int ch = 0; ch < 4; ch++) {
#pragma unroll
            for (int nf = 0; nf < 8; nf++) {
                const __half* kp = kc + (nf * 8 + qrow) * 72 + ch * 16 + 2 * qk;
                uint32_t b0 = *(const uint32_t*)kp;
                uint32_t b1 = *(const uint32_t*)(kp + 8);
                mma_f16(sc[nf], qa[ch][0], qa[ch][1], qa[ch][2], qa[ch][3], b0, b1);
            }
        }

        if (kt == kt_diag) {
#pragma unroll
            for (int nf = 0; nf < 8; nf++) {
                int c = kt * 64 + nf * 8 + qk * 2;
                if (c > r0g)     sc[nf][0] = -1e30f;
                if (c + 1 > r0g) sc[nf][1] = -1e30f;
                if (c > r1g)     sc[nf][2] = -1e30f;
                if (c + 1 > r1g) sc[nf][3] = -1e30f;
            }
        }

        float mx0 = -1e30f, mx1 = -1e30f;
#pragma unroll
        for (int nf = 0; nf < 8; nf++) {
            mx0 = fmaxf(mx0, fmaxf(sc[nf][0], sc[nf][1]));
            mx1 = fmaxf(mx1, fmaxf(sc[nf][2], sc[nf][3]));
        }
        mx0 = fmaxf(mx0, __shfl_xor_sync(0xffffffffu, mx0, 1));
        mx0 = fmaxf(mx0, __shfl_xor_sync(0xffffffffu, mx0, 2));
        mx1 = fmaxf(mx1, __shfl_xor_sync(0xffffffffu, mx1, 1));
        mx1 = fmaxf(mx1, __shfl_xor_sync(0xffffffffu, mx1, 2));
        float mn0 = fmaxf(m0, mx0), mn1 = fmaxf(m1, mx1);
        float al0 = ex2f(m0 - mn0), al1 = ex2f(m1 - mn1);
        float s0 = 0.f, s1 = 0.f;
#pragma unroll
        for (int nf = 0; nf < 8; nf++) {
            sc[nf][0] = ex2f(sc[nf][0] - mn0);
            sc[nf][1] = ex2f(sc[nf][1] - mn0);
            sc[nf][2] = ex2f(sc[nf][2] - mn1);
            sc[nf][3] = ex2f(sc[nf][3] - mn1);
            s0 += sc[nf][0] + sc[nf][1];
            s1 += sc[nf][2] + sc[nf][3];
        }
        s0 += __shfl_xor_sync(0xffffffffu, s0, 1);
        s0 += __shfl_xor_sync(0xffffffffu, s0, 2);
        s1 += __shfl_xor_sync(0xffffffffu, s1, 1);
        s1 += __shfl_xor_sync(0xffffffffu, s1, 2);
        l0 = l0 * al0 + s0;  m0 = mn0;
        l1 = l1 * al1 + s1;  m1 = mn1;
#pragma unroll
        for (int nf = 0; nf < 8; nf++) {
            o[nf][0] *= al0; o[nf][1] *= al0;
            o[nf][2] *= al1; o[nf][3] *= al1;
        }

        const uint32_t vc_u = vs_u + cur * STG * 2;
#pragma unroll
        for (int jk = 0; jk < 4; jk++) {
            uint32_t a0 = h2pack(sc[2*jk][0],   sc[2*jk][1]);
            uint32_t a1 = h2pack(sc[2*jk][2],   sc[2*jk][3]);
            uint32_t a2 = h2pack(sc[2*jk+1][0], sc[2*jk+1][1]);
            uint32_t a3 = h2pack(sc[2*jk+1][2], sc[2*jk+1][3]);
            uint32_t vaddr_row = jk * 16 + (lane & 15);
#pragma unroll
            for (int jn = 0; jn < 8; jn++) {
                uint32_t b0, b1;
                ldsm_x2_trans(b0, b1, vc_u + vaddr_row * 144 + jn * 16);
                mma_f16(o[jn], a0, a1, a2, a3, b0, b1);
            }
        }
    }

    float inv0 = 1.0f / (l0 + 1e-8f);
    float inv1 = 1.0f / (l1 + 1e-8f);
    __half* op0 = O + (size_t)(b * NN + r0g) * HID + h * DD;
    __half* op1 = O + (size_t)(b * NN + r1g) * HID + h * DD;
#pragma unroll
    for (int nf = 0; nf < 8; nf++) {
        int d = nf * 8 + qk * 2;
        *(uint32_t*)(op0 + d) = h2pack(o[nf][0] * inv0, o[nf][1] * inv0);
        *(uint32_t*)(op1 + d) = h2pack(o[nf][2] * inv1, o[nf][3] * inv1);
    }
}

// ============================================================
extern "C" void kernel_launch(void* const* d_in, const int* in_sizes, int n_in,
                              void* d_out, int out_size)
{
    const float* hs  = (const float*)d_in[0];
    const int*   pos = (const int*)d_in[1];
    const float* q_w = (const float*)d_in[2];
    const float* q_b = (const float*)d_in[3];
    const float* k_w = (const float*)d_in[4];
    const float* k_b = (const float*)d_in[5];
    const float* v_w = (const float*)d_in[6];
    const float* v_b = (const float*)d_in[7];
    const float* o_w = (const float*)d_in[8];
    float* out = (float*)d_out;

    float *pqkv, *pbqkv;
    __half *pkvh, *poh, *phsh, *pwqkvh, *powh;
    cudaGetSymbolAddress((void**)&pqkv,   g_qkv);
    cudaGetSymbolAddress((void**)&pkvh,   g_kvh);
    cudaGetSymbolAddress((void**)&poh,    g_oh);
    cudaGetSymbolAddress((void**)&phsh,   g_hsh);
    cudaGetSymbolAddress((void**)&pwqkvh, g_wqkvh);
    cudaGetSymbolAddress((void**)&pbqkv,  g_bqkv);
    cudaGetSymbolAddress((void**)&powh,   g_owh);

    const int GEMM_SMEM = 2 * (128*72 + 64*136) * 2;   // 71680 B
    const int ATTN_SMEM = 2 * (64*72 + 64*72) * 2;     // 36864 B
    cudaFuncSetAttribute(gemm_h,   cudaFuncAttributeMaxDynamicSharedMemorySize, GEMM_SMEM);
    cudaFuncSetAttribute(attn_mma, cudaFuncAttributeMaxDynamicSharedMemorySize, ATTN_SMEM);

    // prep (all coalesced): hs->fp16, o_w->fp16 (same layout), pack qkv
    {
        int n4 = MTOT * HID / 4;
        f2h4_kernel<<<(n4 + 255) / 256, 256>>>((const float4*)hs, phsh, n4);
        int m4 = HID * HID / 4;
        f2h4_kernel<<<(m4 + 255) / 256, 256>>>((const float4*)o_w, powh, m4);
        int tp = HID * NQKV;
        pack_qkv_kernel<<<(tp + 255) / 256, 256>>>(q_w, k_w, v_w, q_b, k_b, v_b,
                                                   pwqkvh, pbqkv);
    }
    // fused QKV projection: [4096,896]h @ [896,1152]h + b -> fp32
    gemm_h<<<dim3(9, 32), 256, GEMM_SMEM>>>(phsh, pwqkvh, pbqkv, pqkv, NQKV, NQKV, HID);
    // RoPE: Q fp32 in place; K roped->fp16; V converted->fp16
    {
        int tot = MTOT * 18 * 32;
        rope_qkv<<<(tot + 255) / 256, 256>>>(pqkv, pkvh, pos);
    }
    // causal GQA attention -> fp16 O
    attn_mma<<<dim3(BB * HQ, NN / 64), 128, ATTN_SMEM>>>(pqkv, pkvh, poh);
    // output projection: [4096,896]h @ [896,896]h -> fp32 out
    gemm_h<<<dim3(7, 32), 256, GEMM_SMEM>>>(poh, powh, nullptr, out, HID, HID, HID);
}